// round 2
// baseline (speedup 1.0000x reference)
#include <cuda_runtime.h>
#include <math.h>

#define B_    2
#define N_    6
#define FD    128
#define DIM   128
#define H_    64
#define W_    176
#define P_    (H_*W_)          // 11264
#define BNV   (B_*N_)          // 12
#define T2    (B_*P_)          // 22528
#define IMG_W_ 704.0f
#define IMG_H_ 256.0f

// ---------------- scratch (static device memory, allowed) ----------------
__device__ float g_Hm[BNV*9];
__device__ float g_bns[FD];
__device__ float g_bnt[FD];
__device__ float g_Wt[FD*DIM];                       // conv_w transposed [c][o]
__device__ float g_val[(size_t)BNV*P_*DIM];          // conv out, pixel-major
__device__ float g_zln[(size_t)T2*DIM];              // post-LN1, token-major
__device__ float g_zlnT[(size_t)DIM*T2];             // post-LN1, dim-major
__device__ float g_HT[(size_t)(2*DIM)*T2];           // MLP hidden, j-major

__device__ __forceinline__ float wsum(float v) {
    #pragma unroll
    for (int o = 16; o > 0; o >>= 1) v += __shfl_xor_sync(0xFFFFFFFFu, v, o);
    return v;
}

__device__ __forceinline__ float gelu_exact(float x) {
    return 0.5f * x * (1.0f + erff(x * 0.70710678118654752f));
}

// ---------------- K0: homographies + BN fold + W transpose ----------------
__global__ void k_setup(const float* __restrict__ I_src, const float* __restrict__ I_tar_inv,
                        const float* __restrict__ E, const float* __restrict__ dis,
                        const float* __restrict__ nrm, const float* __restrict__ conv_w,
                        const float* __restrict__ bg, const float* __restrict__ bb,
                        const float* __restrict__ bm, const float* __restrict__ bv) {
    int t = threadIdx.x;
    if (t < BNV) {
        int b = t / N_;
        float ds = dis[b];
        float M[9], A[9];
        #pragma unroll
        for (int i = 0; i < 3; i++) {
            float Ti = E[t*16 + i*4 + 3];
            #pragma unroll
            for (int j = 0; j < 3; j++)
                M[i*3+j] = E[t*16 + i*4 + j] - Ti * nrm[b*3+j] / ds;
        }
        #pragma unroll
        for (int i = 0; i < 3; i++)
            #pragma unroll
            for (int j = 0; j < 3; j++) {
                float s = 0.f;
                #pragma unroll
                for (int k = 0; k < 3; k++) s += I_src[t*9 + i*3 + k] * M[k*3+j];
                A[i*3+j] = s;
            }
        #pragma unroll
        for (int i = 0; i < 3; i++)
            #pragma unroll
            for (int j = 0; j < 3; j++) {
                float s = 0.f;
                #pragma unroll
                for (int k = 0; k < 3; k++) s += A[i*3+k] * I_tar_inv[b*9 + k*3 + j];
                g_Hm[t*9 + i*3 + j] = s;
            }
    }
    if (t < FD) {
        float s = bg[t] / sqrtf(bv[t] + 1e-5f);
        g_bns[t] = s;
        g_bnt[t] = bb[t] - bm[t] * s;
    }
    for (int i = t; i < FD*DIM; i += blockDim.x) {
        int o = i / FD, c = i % FD;          // conv_w[o][c]
        g_Wt[c*DIM + o] = conv_w[i];
    }
}

// ---------------- K1: BN+ReLU + 1x1 conv GEMM -> val (bn, p, d) ----------------
__global__ void __launch_bounds__(256) k_conv(const float* __restrict__ feat) {
    __shared__ float Ws[64*128];   // [c][o]
    __shared__ float Xs[64*64];    // [c][p]
    int bn = blockIdx.y;
    int p0 = blockIdx.x * 64;
    int t = threadIdx.x;
    int pg = t & 15;               // 4 pixels
    int og = t >> 4;               // 8 outputs
    float acc[4][8];
    #pragma unroll
    for (int i = 0; i < 4; i++)
        #pragma unroll
        for (int j = 0; j < 8; j++) acc[i][j] = 0.f;

    for (int c0 = 0; c0 < FD; c0 += 64) {
        for (int i = t; i < 64*128; i += 256)
            Ws[i] = g_Wt[(size_t)(c0 + (i >> 7)) * DIM + (i & 127)];
        for (int i = t; i < 64*64; i += 256) {
            int c = i >> 6, p = i & 63;
            float x = feat[((size_t)bn*FD + c0 + c) * P_ + p0 + p];
            x = fmaf(x, g_bns[c0+c], g_bnt[c0+c]);
            Xs[i] = fmaxf(x, 0.f);
        }
        __syncthreads();
        #pragma unroll 8
        for (int c = 0; c < 64; ++c) {
            float4 xv = *(const float4*)&Xs[c*64 + pg*4];
            float4 wa = *(const float4*)&Ws[c*128 + og*8];
            float4 wb = *(const float4*)&Ws[c*128 + og*8 + 4];
            float xr[4] = {xv.x, xv.y, xv.z, xv.w};
            float wr[8] = {wa.x, wa.y, wa.z, wa.w, wb.x, wb.y, wb.z, wb.w};
            #pragma unroll
            for (int i = 0; i < 4; i++)
                #pragma unroll
                for (int j = 0; j < 8; j++)
                    acc[i][j] = fmaf(xr[i], wr[j], acc[i][j]);
        }
        __syncthreads();
    }
    #pragma unroll
    for (int i = 0; i < 4; i++) {
        int p = p0 + pg*4 + i;
        float* dst = &g_val[((size_t)bn*P_ + p) * DIM + og*8];
        *(float4*)dst       = make_float4(acc[i][0], acc[i][1], acc[i][2], acc[i][3]);
        *(float4*)(dst + 4) = make_float4(acc[i][4], acc[i][5], acc[i][6], acc[i][7]);
    }
}

// ---------------- K2: uv + bilinear + attention + residual + LN1 ----------------
__global__ void __launch_bounds__(256) k_attn(const float* __restrict__ ln1g,
                                              const float* __restrict__ ln1b) {
    __shared__ float sHm[BNV*9];
    __shared__ float sZ[DIM*9];    // padded transpose staging [d][warp]
    int t = threadIdx.x;
    if (t < BNV*9) sHm[t] = g_Hm[t];
    __syncthreads();

    int warp = t >> 5, lane = t & 31;
    int pix = blockIdx.x * 8 + warp;        // global token
    int b = pix / P_;
    int p = pix - b * P_;
    int x = p % W_, y = p / W_;
    float px = ((float)x / (float)(W_-1)) * IMG_W_;
    float py = ((float)y / (float)(H_-1)) * IMG_H_;
    int d0 = lane << 2;

    const float4 q4 = *(const float4*)&g_val[((size_t)(b*N_)*P_ + p) * DIM + d0];
    float qs = q4.x*q4.x + q4.y*q4.y + q4.z*q4.z + q4.w*q4.w;
    qs = wsum(qs);
    float qinv = 1.0f / fmaxf(sqrtf(qs), 1e-12f);

    float vb[N_][4];
    float dot[N_];
    #pragma unroll
    for (int n = 0; n < N_; n++) {
        int bn = b*N_ + n;
        const float* Hm = &sHm[bn*9];
        float hx = Hm[0]*px + Hm[1]*py + Hm[2];
        float hy = Hm[3]*px + Hm[4]*py + Hm[5];
        float hz = Hm[6]*px + Hm[7]*py + Hm[8];
        float ux = ((hx / hz) / IMG_W_) * (float)W_;
        float uy = ((hy / hz) / IMG_H_) * (float)H_;
        float fx = floorf(ux), fy = floorf(uy);
        float wx = ux - fx,  wy = uy - fy;
        float validf = (ux >= 0.f && ux <= (float)(W_-1) &&
                        uy >= 0.f && uy <= (float)(H_-1)) ? 1.0f : 0.0f;
        int x0 = min(max((int)fx, 0), W_-1);
        int x1 = min(x0+1, W_-1);
        int y0 = min(max((int)fy, 0), H_-1);
        int y1 = min(y0+1, H_-1);
        float w00 = (1.f-wx)*(1.f-wy), w01 = wx*(1.f-wy);
        float w10 = (1.f-wx)*wy,       w11 = wx*wy;
        const float* base = &g_val[(size_t)bn*P_*DIM + d0];
        float4 a00 = *(const float4*)&base[(size_t)(y0*W_+x0)*DIM];
        float4 a01 = *(const float4*)&base[(size_t)(y0*W_+x1)*DIM];
        float4 a10 = *(const float4*)&base[(size_t)(y1*W_+x0)*DIM];
        float4 a11 = *(const float4*)&base[(size_t)(y1*W_+x1)*DIM];
        float v0 = a00.x*w00 + a01.x*w01 + a10.x*w10 + a11.x*w11;
        float v1 = a00.y*w00 + a01.y*w01 + a10.y*w10 + a11.y*w11;
        float v2 = a00.z*w00 + a01.z*w01 + a10.z*w10 + a11.z*w11;
        float v3 = a00.w*w00 + a01.w*w01 + a10.w*w10 + a11.w*w11;
        vb[n][0] = v0; vb[n][1] = v1; vb[n][2] = v2; vb[n][3] = v3;
        float ss = v0*v0 + v1*v1 + v2*v2 + v3*v3;
        float dd = q4.x*v0 + q4.y*v1 + q4.z*v2 + q4.w*v3;
        ss = wsum(ss); dd = wsum(dd);
        float kinv = 1.0f / fmaxf(sqrtf(ss), 1e-12f);
        dot[n] = dd * qinv * kinv * validf;
    }
    float m = dot[0];
    #pragma unroll
    for (int n = 1; n < N_; n++) m = fmaxf(m, dot[n]);
    float e[N_], s = 0.f;
    #pragma unroll
    for (int n = 0; n < N_; n++) { e[n] = expf(dot[n] - m); s += e[n]; }
    float sinv = 1.0f / s;
    float z[4] = {q4.x, q4.y, q4.z, q4.w};
    #pragma unroll
    for (int n = 0; n < N_; n++) {
        float a = e[n] * sinv;
        #pragma unroll
        for (int i = 0; i < 4; i++) z[i] = fmaf(a, vb[n][i], z[i]);
    }
    // LN1 (two-pass, matches jnp.var)
    float ls = z[0] + z[1] + z[2] + z[3];
    ls = wsum(ls);
    float mean = ls * (1.0f / DIM);
    float vv = 0.f;
    #pragma unroll
    for (int i = 0; i < 4; i++) { float d = z[i] - mean; vv += d*d; }
    vv = wsum(vv);
    float rstd = 1.0f / sqrtf(vv * (1.0f / DIM) + 1e-5f);
    float4 g4 = *(const float4*)&ln1g[d0];
    float4 b4 = *(const float4*)&ln1b[d0];
    float zn[4];
    zn[0] = (z[0]-mean)*rstd*g4.x + b4.x;
    zn[1] = (z[1]-mean)*rstd*g4.y + b4.y;
    zn[2] = (z[2]-mean)*rstd*g4.z + b4.z;
    zn[3] = (z[3]-mean)*rstd*g4.w + b4.w;
    *(float4*)&g_zln[(size_t)pix*DIM + d0] = make_float4(zn[0], zn[1], zn[2], zn[3]);
    #pragma unroll
    for (int i = 0; i < 4; i++) sZ[(d0+i)*9 + warp] = zn[i];
    __syncthreads();
    size_t pb = (size_t)blockIdx.x * 8;
    for (int i = t; i < DIM*8; i += 256) {
        int d = i >> 3, tok = i & 7;
        g_zlnT[(size_t)d*T2 + pb + tok] = sZ[d*9 + tok];
    }
}

// ---------------- K3: MLP layer 1 (+b1, exact GELU) -> H_T [j][t] ----------------
__global__ void __launch_bounds__(256) k_mlp1(const float* __restrict__ w1,
                                              const float* __restrict__ b1) {
    __shared__ float Ws[64*128];   // [c][j]
    __shared__ float Zs[64*64];    // [c][tok]
    int t0 = blockIdx.x * 64;
    int j0 = blockIdx.y * 128;
    int t = threadIdx.x;
    int tg = t & 15, jg = t >> 4;
    float acc[4][8];
    #pragma unroll
    for (int i = 0; i < 4; i++)
        #pragma unroll
        for (int j = 0; j < 8; j++) acc[i][j] = 0.f;

    for (int c0 = 0; c0 < DIM; c0 += 64) {
        for (int i = t; i < 64*128; i += 256)
            Ws[i] = w1[(size_t)(c0 + (i >> 7)) * (2*DIM) + j0 + (i & 127)];
        for (int i = t; i < 64*64; i += 256)
            Zs[i] = g_zlnT[(size_t)(c0 + (i >> 6)) * T2 + t0 + (i & 63)];
        __syncthreads();
        #pragma unroll 8
        for (int c = 0; c < 64; ++c) {
            float4 xv = *(const float4*)&Zs[c*64 + tg*4];
            float4 wa = *(const float4*)&Ws[c*128 + jg*8];
            float4 wb = *(const float4*)&Ws[c*128 + jg*8 + 4];
            float xr[4] = {xv.x, xv.y, xv.z, xv.w};
            float wr[8] = {wa.x, wa.y, wa.z, wa.w, wb.x, wb.y, wb.z, wb.w};
            #pragma unroll
            for (int i = 0; i < 4; i++)
                #pragma unroll
                for (int j = 0; j < 8; j++)
                    acc[i][j] = fmaf(xr[i], wr[j], acc[i][j]);
        }
        __syncthreads();
    }
    #pragma unroll
    for (int j = 0; j < 8; j++) {
        int jj = j0 + jg*8 + j;
        float bj = b1[jj];
        float4 o = make_float4(gelu_exact(acc[0][j] + bj), gelu_exact(acc[1][j] + bj),
                               gelu_exact(acc[2][j] + bj), gelu_exact(acc[3][j] + bj));
        *(float4*)&g_HT[(size_t)jj*T2 + t0 + tg*4] = o;
    }
}

// ---------------- K4: MLP layer 2 + residual + LN2 + transposed store ----------------
__global__ void __launch_bounds__(256) k_mlp2(const float* __restrict__ w2,
                                              const float* __restrict__ b2,
                                              const float* __restrict__ g2,
                                              const float* __restrict__ bb2,
                                              float* __restrict__ out) {
    __shared__ float Ws[32*128];   // [c][d]
    __shared__ float Hs[32*64];    // [c][tok]
    __shared__ float ps[16*64];
    __shared__ float pq[16*64];
    __shared__ float smean[64];
    __shared__ float srstd[64];
    int t0 = blockIdx.x * 64;
    int t = threadIdx.x;
    int tg = t & 15, dg = t >> 4;
    float acc[4][8];
    #pragma unroll
    for (int i = 0; i < 4; i++)
        #pragma unroll
        for (int j = 0; j < 8; j++) acc[i][j] = 0.f;

    for (int c0 = 0; c0 < 2*DIM; c0 += 32) {
        for (int i = t; i < 32*128; i += 256)
            Ws[i] = w2[(size_t)(c0 + (i >> 7)) * DIM + (i & 127)];
        for (int i = t; i < 32*64; i += 256)
            Hs[i] = g_HT[(size_t)(c0 + (i >> 6)) * T2 + t0 + (i & 63)];
        __syncthreads();
        #pragma unroll 8
        for (int c = 0; c < 32; ++c) {
            float4 xv = *(const float4*)&Hs[c*64 + tg*4];
            float4 wa = *(const float4*)&Ws[c*128 + dg*8];
            float4 wb = *(const float4*)&Ws[c*128 + dg*8 + 4];
            float xr[4] = {xv.x, xv.y, xv.z, xv.w};
            float wr[8] = {wa.x, wa.y, wa.z, wa.w, wb.x, wb.y, wb.z, wb.w};
            #pragma unroll
            for (int i = 0; i < 4; i++)
                #pragma unroll
                for (int j = 0; j < 8; j++)
                    acc[i][j] = fmaf(xr[i], wr[j], acc[i][j]);
        }
        __syncthreads();
    }
    float bw[8];
    #pragma unroll
    for (int j = 0; j < 8; j++) bw[j] = b2[dg*8 + j];
    #pragma unroll
    for (int i = 0; i < 4; i++) {
        int tok = tg*4 + i;
        const float* zr = &g_zln[(size_t)(t0 + tok) * DIM + dg*8];
        float4 z0 = *(const float4*)zr;
        float4 z1 = *(const float4*)(zr + 4);
        float zrr[8] = {z0.x, z0.y, z0.z, z0.w, z1.x, z1.y, z1.z, z1.w};
        float s = 0.f, q = 0.f;
        #pragma unroll
        for (int j = 0; j < 8; j++) {
            float v = acc[i][j] + bw[j] + zrr[j];
            acc[i][j] = v;
            s += v; q += v*v;
        }
        ps[dg*64 + tok] = s;
        pq[dg*64 + tok] = q;
    }
    __syncthreads();
    if (t < 64) {
        float s = 0.f, q = 0.f;
        #pragma unroll
        for (int g = 0; g < 16; g++) { s += ps[g*64 + t]; q += pq[g*64 + t]; }
        float mean = s * (1.0f / DIM);
        float var  = fmaxf(q * (1.0f / DIM) - mean*mean, 0.0f);
        smean[t] = mean;
        srstd[t] = 1.0f / sqrtf(var + 1e-5f);
    }
    __syncthreads();
    int b = t0 / P_;
    int prem = t0 - b * P_ + tg*4;
    #pragma unroll
    for (int j = 0; j < 8; j++) {
        int d = dg*8 + j;
        float gg = g2[d], bb = bb2[d];
        float v0 = (acc[0][j] - smean[tg*4+0]) * srstd[tg*4+0] * gg + bb;
        float v1 = (acc[1][j] - smean[tg*4+1]) * srstd[tg*4+1] * gg + bb;
        float v2 = (acc[2][j] - smean[tg*4+2]) * srstd[tg*4+2] * gg + bb;
        float v3 = (acc[3][j] - smean[tg*4+3]) * srstd[tg*4+3] * gg + bb;
        *(float4*)&out[((size_t)b*DIM + d) * P_ + prem] = make_float4(v0, v1, v2, v3);
    }
}

// ---------------- launch ----------------
extern "C" void kernel_launch(void* const* d_in, const int* in_sizes, int n_in,
                              void* d_out, int out_size) {
    const float* feature   = (const float*)d_in[0];
    const float* I_src     = (const float*)d_in[1];
    const float* I_tar_inv = (const float*)d_in[2];
    const float* E         = (const float*)d_in[3];
    const float* dis       = (const float*)d_in[4];
    const float* nrm       = (const float*)d_in[5];
    const float* conv_w    = (const float*)d_in[6];
    const float* bn_gamma  = (const float*)d_in[7];
    const float* bn_beta   = (const float*)d_in[8];
    const float* bn_mean   = (const float*)d_in[9];
    const float* bn_var    = (const float*)d_in[10];
    const float* ln1_g     = (const float*)d_in[11];
    const float* ln1_b     = (const float*)d_in[12];
    const float* ln2_g     = (const float*)d_in[13];
    const float* ln2_b     = (const float*)d_in[14];
    const float* mlp_w1    = (const float*)d_in[15];
    const float* mlp_b1    = (const float*)d_in[16];
    const float* mlp_w2    = (const float*)d_in[17];
    const float* mlp_b2    = (const float*)d_in[18];
    float* out = (float*)d_out;

    k_setup<<<1, 256>>>(I_src, I_tar_inv, E, dis, nrm, conv_w,
                        bn_gamma, bn_beta, bn_mean, bn_var);
    k_conv<<<dim3(P_/64, BNV), 256>>>(feature);
    k_attn<<<T2/8, 256>>>(ln1_g, ln1_b);
    k_mlp1<<<dim3(T2/64, 2), 256>>>(mlp_w1, mlp_b1);
    k_mlp2<<<T2/64, 256>>>(mlp_w2, mlp_b2, ln2_g, ln2_b, out);
}

// round 6
// speedup vs baseline: 1.1290x; 1.1290x over previous
#include <cuda_runtime.h>
#include <cuda_bf16.h>
#include <math.h>
#include <stdint.h>

#define B_    2
#define N_    6
#define FD    128
#define DIM   128
#define H_    64
#define W_    176
#define P_    (H_*W_)          // 11264
#define BNV   (B_*N_)          // 12
#define T2    (B_*P_)          // 22528
#define IMG_W_ 704.0f
#define IMG_H_ 256.0f
#define PAD   136              // bf16 row stride in smem tiles

// ---------------- scratch ----------------
__device__ float    g_Hm[BNV*9];
__device__ float    g_bns[FD];
__device__ float    g_bnt[FD];
__device__ uint32_t g_wcpk[DIM*FD];                  // conv W [o][c], split-packed
__device__ uint32_t g_w1pk[(2*DIM)*DIM];             // w1^T  [j][c], split-packed
__device__ uint32_t g_w2pk[DIM*(2*DIM)];             // w2^T  [d][j], split-packed
__device__ float    g_val[(size_t)BNV*P_*DIM];       // conv out, pixel-major
__device__ float    g_zln[(size_t)T2*DIM];           // post-LN1 fp32 (residual)
__device__ uint32_t g_zpk[(size_t)T2*DIM];           // post-LN1 split-packed
__device__ uint32_t g_hpk[(size_t)T2*(2*DIM)];       // MLP hidden split-packed

#define SMEM_BYTES (4*128*PAD*2)   // 139264: Ah, Al, Bh, Bl bf16 tiles

// ---------------- helpers ----------------
__device__ __forceinline__ float wsum(float v) {
    #pragma unroll
    for (int o = 16; o > 0; o >>= 1) v += __shfl_xor_sync(0xFFFFFFFFu, v, o);
    return v;
}
__device__ __forceinline__ float gelu_exact(float x) {
    return 0.5f * x * (1.0f + erff(x * 0.70710678118654752f));
}
__device__ __forceinline__ uint32_t fsplit(float x) {
    __nv_bfloat16 h = __float2bfloat16(x);
    float r = x - __bfloat162float(h);
    __nv_bfloat16 l = __float2bfloat16(r);
    return (uint32_t)__bfloat16_as_ushort(h) | ((uint32_t)__bfloat16_as_ushort(l) << 16);
}

// ---------------- warp-mma primitives (baseline PTX, no 'a' features) ----------------
__device__ __forceinline__ void ldsm4(uint32_t* r, uint32_t addr) {
    asm volatile("ldmatrix.sync.aligned.m8n8.x4.shared.b16 {%0,%1,%2,%3}, [%4];"
        : "=r"(r[0]), "=r"(r[1]), "=r"(r[2]), "=r"(r[3]) : "r"(addr));
}
__device__ __forceinline__ void ldsm2(uint32_t* r, uint32_t addr) {
    asm volatile("ldmatrix.sync.aligned.m8n8.x2.shared.b16 {%0,%1}, [%2];"
        : "=r"(r[0]), "=r"(r[1]) : "r"(addr));
}
__device__ __forceinline__ void mma_bf16(float* d, const uint32_t* a, const uint32_t* b) {
    asm volatile("mma.sync.aligned.m16n8k16.row.col.f32.bf16.bf16.f32 "
        "{%0,%1,%2,%3}, {%4,%5,%6,%7}, {%8,%9}, {%0,%1,%2,%3};"
        : "+f"(d[0]), "+f"(d[1]), "+f"(d[2]), "+f"(d[3])
        : "r"(a[0]), "r"(a[1]), "r"(a[2]), "r"(a[3]), "r"(b[0]), "r"(b[1]));
}

// packed-uint32 gmem row (hi|lo<<16 per element) -> hi/lo bf16 smem tiles
__device__ __forceinline__ void load_pk_tile(const uint32_t* g, int row_stride, int col_off,
                                             __nv_bfloat16* sh, __nv_bfloat16* sl, int t) {
    for (int idx = t; idx < 128*64; idx += 256) {
        int row = idx >> 6, cp = idx & 63;
        uint2 v = *(const uint2*)(g + (size_t)row * row_stride + col_off + cp * 2);
        *(uint32_t*)&sh[row*PAD + cp*2] = (v.x & 0xFFFFu) | (v.y << 16);
        *(uint32_t*)&sl[row*PAD + cp*2] = (v.x >> 16)     | (v.y & 0xFFFF0000u);
    }
}

// one 128-K chunk: acc[mt][nt][4] += A(128xK) * B^T (B stored [n][k]), 3-term split
__device__ __forceinline__ void gemm128(float acc[4][4][4],
                                        const __nv_bfloat16* sAh, const __nv_bfloat16* sAl,
                                        const __nv_bfloat16* sBh, const __nv_bfloat16* sBl,
                                        int wm, int wn, int lane) {
    uint32_t aH = (uint32_t)__cvta_generic_to_shared(sAh);
    uint32_t aL = (uint32_t)__cvta_generic_to_shared(sAl);
    uint32_t bH = (uint32_t)__cvta_generic_to_shared(sBh);
    uint32_t bL = (uint32_t)__cvta_generic_to_shared(sBl);
    uint32_t aoff = (uint32_t)(wm + (lane & 15)) * (PAD*2) + ((lane >> 4) << 4);
    uint32_t boff = (uint32_t)(wn + (lane & 7))  * (PAD*2) + (((lane >> 3) & 1) << 4);
    #pragma unroll
    for (int kk = 0; kk < 8; kk++) {
        uint32_t kb = (uint32_t)kk * 32;
        uint32_t ah[4][4], al[4][4], bh[4][2], bl[4][2];
        #pragma unroll
        for (int mt = 0; mt < 4; mt++) {
            uint32_t o = aoff + (uint32_t)mt * 16 * (PAD*2) + kb;
            ldsm4(ah[mt], aH + o);
            ldsm4(al[mt], aL + o);
        }
        #pragma unroll
        for (int nt = 0; nt < 4; nt++) {
            uint32_t o = boff + (uint32_t)nt * 8 * (PAD*2) + kb;
            ldsm2(bh[nt], bH + o);
            ldsm2(bl[nt], bL + o);
        }
        #pragma unroll
        for (int mt = 0; mt < 4; mt++)
            #pragma unroll
            for (int nt = 0; nt < 4; nt++) {
                mma_bf16(acc[mt][nt], ah[mt], bh[nt]);
                mma_bf16(acc[mt][nt], ah[mt], bl[nt]);
                mma_bf16(acc[mt][nt], al[mt], bh[nt]);
            }
    }
}

// ---------------- K0: setup ----------------
__global__ void k_setup(const float* __restrict__ I_src, const float* __restrict__ I_tar_inv,
                        const float* __restrict__ E, const float* __restrict__ dis,
                        const float* __restrict__ nrm, const float* __restrict__ conv_w,
                        const float* __restrict__ bg, const float* __restrict__ bb,
                        const float* __restrict__ bm, const float* __restrict__ bv,
                        const float* __restrict__ w1, const float* __restrict__ w2) {
    int t = threadIdx.x;
    if (blockIdx.x == 0) {
        if (t < BNV) {
            int b = t / N_;
            float ds = dis[b];
            float M[9], A[9];
            #pragma unroll
            for (int i = 0; i < 3; i++) {
                float Ti = E[t*16 + i*4 + 3];
                #pragma unroll
                for (int j = 0; j < 3; j++)
                    M[i*3+j] = E[t*16 + i*4 + j] - Ti * nrm[b*3+j] / ds;
            }
            #pragma unroll
            for (int i = 0; i < 3; i++)
                #pragma unroll
                for (int j = 0; j < 3; j++) {
                    float s = 0.f;
                    #pragma unroll
                    for (int k = 0; k < 3; k++) s += I_src[t*9 + i*3 + k] * M[k*3+j];
                    A[i*3+j] = s;
                }
            #pragma unroll
            for (int i = 0; i < 3; i++)
                #pragma unroll
                for (int j = 0; j < 3; j++) {
                    float s = 0.f;
                    #pragma unroll
                    for (int k = 0; k < 3; k++) s += A[i*3+k] * I_tar_inv[b*9 + k*3 + j];
                    g_Hm[t*9 + i*3 + j] = s;
                }
        }
        if (t < FD) {
            float s = bg[t] / sqrtf(bv[t] + 1e-5f);
            g_bns[t] = s;
            g_bnt[t] = bb[t] - bm[t] * s;
        }
    }
    int g = blockIdx.x * blockDim.x + t;
    int stride = gridDim.x * blockDim.x;
    for (int i = g; i < DIM*FD; i += stride)
        g_wcpk[i] = fsplit(conv_w[i]);                       // already [o][c]
    for (int i = g; i < (2*DIM)*DIM; i += stride) {
        int j = i >> 7, c = i & 127;
        g_w1pk[i] = fsplit(w1[c*(2*DIM) + j]);               // -> [j][c]
    }
    for (int i = g; i < DIM*(2*DIM); i += stride) {
        int d = i >> 8, j = i & 255;
        g_w2pk[i] = fsplit(w2[j*DIM + d]);                   // -> [d][j]
    }
}

// ---------------- K1: conv GEMM (HMMA) ----------------
__global__ void __launch_bounds__(256) k_conv_tc(const float* __restrict__ feat) {
    extern __shared__ __nv_bfloat16 smb[];
    __nv_bfloat16* sAh = smb;
    __nv_bfloat16* sAl = smb + 128*PAD;
    __nv_bfloat16* sBh = smb + 2*128*PAD;
    __nv_bfloat16* sBl = smb + 3*128*PAD;
    int t = threadIdx.x, wid = t >> 5, lane = t & 31;
    int bn = blockIdx.y;
    int p0 = blockIdx.x * 128;

    const float* fb = feat + (size_t)bn * FD * P_ + p0;
    for (int idx = t; idx < 128*128; idx += 256) {
        int c = idx >> 7, p = idx & 127;             // consecutive t -> consecutive p
        float x = fmaxf(fmaf(fb[(size_t)c * P_ + p], g_bns[c], g_bnt[c]), 0.f);
        __nv_bfloat16 h = __float2bfloat16(x);
        sAh[p*PAD + c] = h;
        sAl[p*PAD + c] = __float2bfloat16(x - __bfloat162float(h));
    }
    load_pk_tile(g_wcpk, 128, 0, sBh, sBl, t);
    __syncthreads();

    float acc[4][4][4] = {};
    int wm = (wid >> 2) * 64, wn = (wid & 3) * 32;
    gemm128(acc, sAh, sAl, sBh, sBl, wm, wn, lane);

    float* dst = g_val + ((size_t)bn * P_ + p0) * DIM;
    int r0 = wm + (lane >> 2);
    int c0 = wn + (lane & 3) * 2;
    #pragma unroll
    for (int mt = 0; mt < 4; mt++)
        #pragma unroll
        for (int nt = 0; nt < 4; nt++) {
            int row = r0 + mt*16, col = c0 + nt*8;
            *(float2*)&dst[(size_t)row*DIM + col]     = make_float2(acc[mt][nt][0], acc[mt][nt][1]);
            *(float2*)&dst[(size_t)(row+8)*DIM + col] = make_float2(acc[mt][nt][2], acc[mt][nt][3]);
        }
}

// ---------------- K2: uv + bilinear + attention + residual + LN1 ----------------
__global__ void __launch_bounds__(256) k_attn(const float* __restrict__ ln1g,
                                              const float* __restrict__ ln1b) {
    __shared__ float sHm[BNV*9];
    int t = threadIdx.x;
    if (t < BNV*9) sHm[t] = g_Hm[t];
    __syncthreads();

    int warp = t >> 5, lane = t & 31;
    int pix = blockIdx.x * 8 + warp;
    int b = pix / P_;
    int p = pix - b * P_;
    int x = p % W_, y = p / W_;
    float px = ((float)x / (float)(W_-1)) * IMG_W_;
    float py = ((float)y / (float)(H_-1)) * IMG_H_;
    int d0 = lane << 2;

    const float4 q4 = *(const float4*)&g_val[((size_t)(b*N_)*P_ + p) * DIM + d0];
    float qs = q4.x*q4.x + q4.y*q4.y + q4.z*q4.z + q4.w*q4.w;
    qs = wsum(qs);
    float qinv = 1.0f / fmaxf(sqrtf(qs), 1e-12f);

    float vb[N_][4];
    float dot[N_];
    #pragma unroll
    for (int n = 0; n < N_; n++) {
        int bn = b*N_ + n;
        const float* Hm = &sHm[bn*9];
        float hx = Hm[0]*px + Hm[1]*py + Hm[2];
        float hy = Hm[3]*px + Hm[4]*py + Hm[5];
        float hz = Hm[6]*px + Hm[7]*py + Hm[8];
        float ux = ((hx / hz) / IMG_W_) * (float)W_;
        float uy = ((hy / hz) / IMG_H_) * (float)H_;
        float fx = floorf(ux), fy = floorf(uy);
        float wx = ux - fx,  wy = uy - fy;
        float validf = (ux >= 0.f && ux <= (float)(W_-1) &&
                        uy >= 0.f && uy <= (float)(H_-1)) ? 1.0f : 0.0f;
        int x0 = min(max((int)fx, 0), W_-1);
        int x1 = min(x0+1, W_-1);
        int y0 = min(max((int)fy, 0), H_-1);
        int y1 = min(y0+1, H_-1);
        float w00 = (1.f-wx)*(1.f-wy), w01 = wx*(1.f-wy);
        float w10 = (1.f-wx)*wy,       w11 = wx*wy;
        const float* base = &g_val[(size_t)bn*P_*DIM + d0];
        float4 a00 = *(const float4*)&base[(size_t)(y0*W_+x0)*DIM];
        float4 a01 = *(const float4*)&base[(size_t)(y0*W_+x1)*DIM];
        float4 a10 = *(const float4*)&base[(size_t)(y1*W_+x0)*DIM];
        float4 a11 = *(const float4*)&base[(size_t)(y1*W_+x1)*DIM];
        float v0 = a00.x*w00 + a01.x*w01 + a10.x*w10 + a11.x*w11;
        float v1 = a00.y*w00 + a01.y*w01 + a10.y*w10 + a11.y*w11;
        float v2 = a00.z*w00 + a01.z*w01 + a10.z*w10 + a11.z*w11;
        float v3 = a00.w*w00 + a01.w*w01 + a10.w*w10 + a11.w*w11;
        vb[n][0] = v0; vb[n][1] = v1; vb[n][2] = v2; vb[n][3] = v3;
        float ss = v0*v0 + v1*v1 + v2*v2 + v3*v3;
        float dd = q4.x*v0 + q4.y*v1 + q4.z*v2 + q4.w*v3;
        ss = wsum(ss); dd = wsum(dd);
        float kinv = 1.0f / fmaxf(sqrtf(ss), 1e-12f);
        dot[n] = dd * qinv * kinv * validf;
    }
    float m = dot[0];
    #pragma unroll
    for (int n = 1; n < N_; n++) m = fmaxf(m, dot[n]);
    float e[N_], s = 0.f;
    #pragma unroll
    for (int n = 0; n < N_; n++) { e[n] = expf(dot[n] - m); s += e[n]; }
    float sinv = 1.0f / s;
    float z[4] = {q4.x, q4.y, q4.z, q4.w};
    #pragma unroll
    for (int n = 0; n < N_; n++) {
        float a = e[n] * sinv;
        #pragma unroll
        for (int i = 0; i < 4; i++) z[i] = fmaf(a, vb[n][i], z[i]);
    }
    float ls = z[0] + z[1] + z[2] + z[3];
    ls = wsum(ls);
    float mean = ls * (1.0f / DIM);
    float vv = 0.f;
    #pragma unroll
    for (int i = 0; i < 4; i++) { float d = z[i] - mean; vv += d*d; }
    vv = wsum(vv);
    float rstd = 1.0f / sqrtf(vv * (1.0f / DIM) + 1e-5f);
    float4 g4 = *(const float4*)&ln1g[d0];
    float4 b4 = *(const float4*)&ln1b[d0];
    float zn[4];
    zn[0] = (z[0]-mean)*rstd*g4.x + b4.x;
    zn[1] = (z[1]-mean)*rstd*g4.y + b4.y;
    zn[2] = (z[2]-mean)*rstd*g4.z + b4.z;
    zn[3] = (z[3]-mean)*rstd*g4.w + b4.w;
    *(float4*)&g_zln[(size_t)pix*DIM + d0] = make_float4(zn[0], zn[1], zn[2], zn[3]);
    uint4 pk = make_uint4(fsplit(zn[0]), fsplit(zn[1]), fsplit(zn[2]), fsplit(zn[3]));
    *(uint4*)&g_zpk[(size_t)pix*DIM + d0] = pk;
}

// ---------------- K3: MLP1 (HMMA) + bias + exact GELU + split-pack ----------------
__global__ void __launch_bounds__(256) k_mlp1_tc(const float* __restrict__ b1) {
    extern __shared__ __nv_bfloat16 smb[];
    __nv_bfloat16* sAh = smb;
    __nv_bfloat16* sAl = smb + 128*PAD;
    __nv_bfloat16* sBh = smb + 2*128*PAD;
    __nv_bfloat16* sBl = smb + 3*128*PAD;
    int t = threadIdx.x, wid = t >> 5, lane = t & 31;
    int t0 = blockIdx.x * 128;
    int j0 = blockIdx.y * 128;

    load_pk_tile(g_zpk + (size_t)t0 * DIM, DIM, 0, sAh, sAl, t);
    load_pk_tile(g_w1pk + (size_t)j0 * DIM, DIM, 0, sBh, sBl, t);
    __syncthreads();

    float acc[4][4][4] = {};
    int wm = (wid >> 2) * 64, wn = (wid & 3) * 32;
    gemm128(acc, sAh, sAl, sBh, sBl, wm, wn, lane);

    uint32_t* dst = g_hpk + (size_t)t0 * (2*DIM) + j0;
    int r0 = wm + (lane >> 2);
    int c0 = wn + (lane & 3) * 2;
    #pragma unroll
    for (int mt = 0; mt < 4; mt++)
        #pragma unroll
        for (int nt = 0; nt < 4; nt++) {
            int row = r0 + mt*16, col = c0 + nt*8;
            float bj0 = b1[j0 + col], bj1 = b1[j0 + col + 1];
            uint2 o0 = make_uint2(fsplit(gelu_exact(acc[mt][nt][0] + bj0)),
                                  fsplit(gelu_exact(acc[mt][nt][1] + bj1)));
            uint2 o1 = make_uint2(fsplit(gelu_exact(acc[mt][nt][2] + bj0)),
                                  fsplit(gelu_exact(acc[mt][nt][3] + bj1)));
            *(uint2*)&dst[(size_t)row*(2*DIM) + col]     = o0;
            *(uint2*)&dst[(size_t)(row+8)*(2*DIM) + col] = o1;
        }
}

// ---------------- K4: MLP2 (HMMA, K=256) + residual + LN2 + transposed out ----------------
__global__ void __launch_bounds__(256) k_mlp2_tc(const float* __restrict__ b2,
                                                 const float* __restrict__ g2,
                                                 const float* __restrict__ bb2,
                                                 float* __restrict__ out) {
    extern __shared__ __nv_bfloat16 smb[];
    __nv_bfloat16* sAh = smb;
    __nv_bfloat16* sAl = smb + 128*PAD;
    __nv_bfloat16* sBh = smb + 2*128*PAD;
    __nv_bfloat16* sBl = smb + 3*128*PAD;
    int t = threadIdx.x, wid = t >> 5, lane = t & 31;
    int t0 = blockIdx.x * 128;

    float acc[4][4][4] = {};
    int wm = (wid >> 2) * 64, wn = (wid & 3) * 32;

    #pragma unroll 1
    for (int h = 0; h < 2; h++) {
        if (h) __syncthreads();
        load_pk_tile(g_hpk + (size_t)t0 * (2*DIM), 2*DIM, h*128, sAh, sAl, t);
        load_pk_tile(g_w2pk,                       2*DIM, h*128, sBh, sBl, t);
        __syncthreads();
        gemm128(acc, sAh, sAl, sBh, sBl, wm, wn, lane);
    }
    __syncthreads();   // smem reuse below

    float* smT   = (float*)sAh;             // [128][129] fp32
    float* sMean = (float*)sBh;
    float* sRstd = sMean + 128;
    const float* zb = g_zln + (size_t)t0 * DIM;
    int r0 = wm + (lane >> 2);
    int c0 = wn + (lane & 3) * 2;
    #pragma unroll
    for (int mt = 0; mt < 4; mt++)
        #pragma unroll
        for (int nt = 0; nt < 4; nt++) {
            int row = r0 + mt*16, col = c0 + nt*8;
            float b20 = b2[col], b21 = b2[col+1];
            float2 z0 = *(const float2*)&zb[(size_t)row*DIM + col];
            float2 z1 = *(const float2*)&zb[(size_t)(row+8)*DIM + col];
            smT[row*129 + col]       = acc[mt][nt][0] + b20 + z0.x;
            smT[row*129 + col + 1]   = acc[mt][nt][1] + b21 + z0.y;
            smT[(row+8)*129 + col]   = acc[mt][nt][2] + b20 + z1.x;
            smT[(row+8)*129 + col+1] = acc[mt][nt][3] + b21 + z1.y;
        }
    __syncthreads();
    if (t < 128) {
        float s = 0.f, q = 0.f;
        #pragma unroll 8
        for (int c = 0; c < 128; c++) {
            float v = smT[t*129 + c];
            s += v; q += v*v;
        }
        float mean = s * (1.0f / DIM);
        float var  = fmaxf(q * (1.0f / DIM) - mean*mean, 0.0f);
        sMean[t] = mean;
        sRstd[t] = 1.0f / sqrtf(var + 1e-5f);
    }
    __syncthreads();
    int b = t0 / P_;
    int prem = t0 - b * P_;
    #pragma unroll 4
    for (int k = 0; k < 64; k++) {
        int idx = k * 256 + t;
        int d = idx >> 7, p = idx & 127;      // consecutive t -> consecutive p
        float v = smT[p*129 + d];
        out[((size_t)(b*DIM + d))*P_ + prem + p] =
            (v - sMean[p]) * sRstd[p] * g2[d] + bb2[d];
    }
}

// ---------------- launch ----------------
extern "C" void kernel_launch(void* const* d_in, const int* in_sizes, int n_in,
                              void* d_out, int out_size) {
    const float* feature   = (const float*)d_in[0];
    const float* I_src     = (const float*)d_in[1];
    const float* I_tar_inv = (const float*)d_in[2];
    const float* E         = (const float*)d_in[3];
    const float* dis       = (const float*)d_in[4];
    const float* nrm       = (const float*)d_in[5];
    const float* conv_w    = (const float*)d_in[6];
    const float* bn_gamma  = (const float*)d_in[7];
    const float* bn_beta   = (const float*)d_in[8];
    const float* bn_mean   = (const float*)d_in[9];
    const float* bn_var    = (const float*)d_in[10];
    const float* ln1_g     = (const float*)d_in[11];
    const float* ln1_b     = (const float*)d_in[12];
    const float* ln2_g     = (const float*)d_in[13];
    const float* ln2_b     = (const float*)d_in[14];
    const float* mlp_w1    = (const float*)d_in[15];
    const float* mlp_b1    = (const float*)d_in[16];
    const float* mlp_w2    = (const float*)d_in[17];
    const float* mlp_b2    = (const float*)d_in[18];
    float* out = (float*)d_out;

    cudaFuncSetAttribute(k_conv_tc, cudaFuncAttributeMaxDynamicSharedMemorySize, SMEM_BYTES);
    cudaFuncSetAttribute(k_mlp1_tc, cudaFuncAttributeMaxDynamicSharedMemorySize, SMEM_BYTES);
    cudaFuncSetAttribute(k_mlp2_tc, cudaFuncAttributeMaxDynamicSharedMemorySize, SMEM_BYTES);

    k_setup<<<48, 256>>>(I_src, I_tar_inv, E, dis, nrm, conv_w,
                         bn_gamma, bn_beta, bn_mean, bn_var, mlp_w1, mlp_w2);
    k_conv_tc<<<dim3(P_/128, BNV), 256, SMEM_BYTES>>>(feature);
    k_attn<<<T2/8, 256>>>(ln1_g, ln1_b);
    k_mlp1_tc<<<dim3(T2/128, 2), 256, SMEM_BYTES>>>(mlp_b1);
    k_mlp2_tc<<<T2/128, 256, SMEM_BYTES>>>(mlp_b2, ln2_g, ln2_b, out);
}

// round 7
// speedup vs baseline: 1.6938x; 1.5003x over previous
#include <cuda_runtime.h>
#include <cuda_bf16.h>
#include <math.h>
#include <stdint.h>

#define B_    2
#define N_    6
#define FD    128
#define DIM   128
#define H_    64
#define W_    176
#define P_    (H_*W_)          // 11264
#define BNV   (B_*N_)          // 12
#define T2    (B_*P_)          // 22528
#define IMG_W_ 704.0f
#define IMG_H_ 256.0f

// smem tile: 128 rows x 64 bf16 cols, padded to 72 (144 B row stride)
#define KC     64
#define TPAD   72
#define TROWB  144
#define TILE_ELE (128*TPAD)
#define SMEM_BYTES (4*TILE_ELE*2)   // 73728 B: Ah, Al, Bh, Bl

// ---------------- scratch ----------------
__device__ float         g_Hm[BNV*9];
__device__ float         g_bns[FD];
__device__ float         g_bnt[FD];
__device__ __nv_bfloat16 g_wch[DIM*FD],        g_wcl[DIM*FD];         // conv W [o][c]
__device__ __nv_bfloat16 g_w1h[(2*DIM)*DIM],   g_w1l[(2*DIM)*DIM];    // w1^T [j][c]
__device__ __nv_bfloat16 g_w2h[DIM*(2*DIM)],   g_w2l[DIM*(2*DIM)];    // w2^T [d][j]
__device__ float         g_val[(size_t)BNV*P_*DIM];                    // conv out [bn][p][d]
__device__ float         g_zln[(size_t)T2*DIM];                        // post-LN1 fp32
__device__ __nv_bfloat16 g_zh[(size_t)T2*DIM], g_zl[(size_t)T2*DIM];  // post-LN1 split
__device__ __nv_bfloat16 g_hh[(size_t)T2*(2*DIM)], g_hl[(size_t)T2*(2*DIM)]; // hidden split

// ---------------- helpers ----------------
__device__ __forceinline__ float wsum(float v) {
    #pragma unroll
    for (int o = 16; o > 0; o >>= 1) v += __shfl_xor_sync(0xFFFFFFFFu, v, o);
    return v;
}
__device__ __forceinline__ float gelu_exact(float x) {
    return 0.5f * x * (1.0f + erff(x * 0.70710678118654752f));
}
__device__ __forceinline__ void split2(float x, __nv_bfloat16& h, __nv_bfloat16& l) {
    h = __float2bfloat16(x);
    l = __float2bfloat16(x - __bfloat162float(h));
}
__device__ __forceinline__ uint32_t pack2(__nv_bfloat16 a, __nv_bfloat16 b) {
    return (uint32_t)__bfloat16_as_ushort(a) | ((uint32_t)__bfloat16_as_ushort(b) << 16);
}

// ---------------- async copy ----------------
__device__ __forceinline__ void cpa16(uint32_t s, const void* g) {
    asm volatile("cp.async.cg.shared.global [%0], [%1], 16;" :: "r"(s), "l"(g));
}
__device__ __forceinline__ void cpa_commit_wait() {
    asm volatile("cp.async.commit_group;");
    asm volatile("cp.async.wait_group 0;");
}
// 128 rows x 64 cols chunk of a row-major bf16 plane -> padded smem tile
__device__ __forceinline__ void load_plane(const __nv_bfloat16* g, int rstride, int c0,
                                           __nv_bfloat16* sm, int t) {
    uint32_t sbase = (uint32_t)__cvta_generic_to_shared(sm);
    #pragma unroll
    for (int k = 0; k < 4; k++) {
        int i = k * 256 + t;
        int row = i >> 3, seg = i & 7;
        cpa16(sbase + row*TROWB + seg*16, g + (size_t)row*rstride + c0 + seg*8);
    }
}

// ---------------- warp-mma primitives ----------------
__device__ __forceinline__ void ldsm4(uint32_t* r, uint32_t addr) {
    asm volatile("ldmatrix.sync.aligned.m8n8.x4.shared.b16 {%0,%1,%2,%3}, [%4];"
        : "=r"(r[0]), "=r"(r[1]), "=r"(r[2]), "=r"(r[3]) : "r"(addr));
}
__device__ __forceinline__ void ldsm2(uint32_t* r, uint32_t addr) {
    asm volatile("ldmatrix.sync.aligned.m8n8.x2.shared.b16 {%0,%1}, [%2];"
        : "=r"(r[0]), "=r"(r[1]) : "r"(addr));
}
__device__ __forceinline__ void mma_bf16(float* d, const uint32_t* a, const uint32_t* b) {
    asm volatile("mma.sync.aligned.m16n8k16.row.col.f32.bf16.bf16.f32 "
        "{%0,%1,%2,%3}, {%4,%5,%6,%7}, {%8,%9}, {%0,%1,%2,%3};"
        : "+f"(d[0]), "+f"(d[1]), "+f"(d[2]), "+f"(d[3])
        : "r"(a[0]), "r"(a[1]), "r"(a[2]), "r"(a[3]), "r"(b[0]), "r"(b[1]));
}

// one K=64 chunk: acc += A(128x64) * B^T(128x64), 3-term bf16 split
__device__ __forceinline__ void gemm64(float acc[4][4][4],
                                       const __nv_bfloat16* sAh, const __nv_bfloat16* sAl,
                                       const __nv_bfloat16* sBh, const __nv_bfloat16* sBl,
                                       int wm, int wn, int lane) {
    uint32_t aH = (uint32_t)__cvta_generic_to_shared(sAh);
    uint32_t aL = (uint32_t)__cvta_generic_to_shared(sAl);
    uint32_t bH = (uint32_t)__cvta_generic_to_shared(sBh);
    uint32_t bL = (uint32_t)__cvta_generic_to_shared(sBl);
    uint32_t aoff = (uint32_t)(wm + (lane & 15)) * TROWB + ((lane >> 4) << 4);
    uint32_t boff = (uint32_t)(wn + (lane & 7))  * TROWB + (((lane >> 3) & 1) << 4);
    #pragma unroll
    for (int kk = 0; kk < 4; kk++) {
        uint32_t kb = (uint32_t)kk * 32;
        uint32_t ah[4][4], al[4][4], bh[4][2], bl[4][2];
        #pragma unroll
        for (int mt = 0; mt < 4; mt++) {
            uint32_t o = aoff + (uint32_t)mt * 16 * TROWB + kb;
            ldsm4(ah[mt], aH + o);
            ldsm4(al[mt], aL + o);
        }
        #pragma unroll
        for (int nt = 0; nt < 4; nt++) {
            uint32_t o = boff + (uint32_t)nt * 8 * TROWB + kb;
            ldsm2(bh[nt], bH + o);
            ldsm2(bl[nt], bL + o);
        }
        #pragma unroll
        for (int mt = 0; mt < 4; mt++)
            #pragma unroll
            for (int nt = 0; nt < 4; nt++) {
                mma_bf16(acc[mt][nt], ah[mt], bh[nt]);
                mma_bf16(acc[mt][nt], ah[mt], bl[nt]);
                mma_bf16(acc[mt][nt], al[mt], bh[nt]);
            }
    }
}

// ---------------- K0: setup ----------------
__global__ void k_setup(const float* __restrict__ I_src, const float* __restrict__ I_tar_inv,
                        const float* __restrict__ E, const float* __restrict__ dis,
                        const float* __restrict__ nrm, const float* __restrict__ conv_w,
                        const float* __restrict__ bg, const float* __restrict__ bb,
                        const float* __restrict__ bm, const float* __restrict__ bv,
                        const float* __restrict__ w1, const float* __restrict__ w2) {
    int t = threadIdx.x;
    if (blockIdx.x == 0) {
        if (t < BNV) {
            int b = t / N_;
            float ds = dis[b];
            float M[9], A[9];
            #pragma unroll
            for (int i = 0; i < 3; i++) {
                float Ti = E[t*16 + i*4 + 3];
                #pragma unroll
                for (int j = 0; j < 3; j++)
                    M[i*3+j] = E[t*16 + i*4 + j] - Ti * nrm[b*3+j] / ds;
            }
            #pragma unroll
            for (int i = 0; i < 3; i++)
                #pragma unroll
                for (int j = 0; j < 3; j++) {
                    float s = 0.f;
                    #pragma unroll
                    for (int k = 0; k < 3; k++) s += I_src[t*9 + i*3 + k] * M[k*3+j];
                    A[i*3+j] = s;
                }
            #pragma unroll
            for (int i = 0; i < 3; i++)
                #pragma unroll
                for (int j = 0; j < 3; j++) {
                    float s = 0.f;
                    #pragma unroll
                    for (int k = 0; k < 3; k++) s += A[i*3+k] * I_tar_inv[b*9 + k*3 + j];
                    g_Hm[t*9 + i*3 + j] = s;
                }
        }
        if (t < FD) {
            float s = bg[t] / sqrtf(bv[t] + 1e-5f);
            g_bns[t] = s;
            g_bnt[t] = bb[t] - bm[t] * s;
        }
    }
    int g = blockIdx.x * blockDim.x + t;
    int stride = gridDim.x * blockDim.x;
    for (int i = g; i < DIM*FD; i += stride)
        split2(conv_w[i], g_wch[i], g_wcl[i]);               // already [o][c]
    for (int i = g; i < (2*DIM)*DIM; i += stride) {
        int j = i >> 7, c = i & 127;
        split2(w1[c*(2*DIM) + j], g_w1h[i], g_w1l[i]);       // -> [j][c]
    }
    for (int i = g; i < DIM*(2*DIM); i += stride) {
        int d = i >> 8, j = i & 255;
        split2(w2[j*DIM + d], g_w2h[i], g_w2l[i]);           // -> [d][j]
    }
}

// ---------------- K1: conv GEMM (HMMA, chunked) ----------------
__global__ void __launch_bounds__(256, 2) k_conv_tc(const float* __restrict__ feat) {
    extern __shared__ __nv_bfloat16 smb[];
    __nv_bfloat16* sAh = smb;
    __nv_bfloat16* sAl = smb + TILE_ELE;
    __nv_bfloat16* sBh = smb + 2*TILE_ELE;
    __nv_bfloat16* sBl = smb + 3*TILE_ELE;
    int t = threadIdx.x, wid = t >> 5, lane = t & 31;
    int bn = blockIdx.y;
    int p0 = blockIdx.x * 128;

    float acc[4][4][4] = {};
    int wm = (wid >> 2) * 64, wn = (wid & 3) * 32;
    const float* fb = feat + (size_t)bn * FD * P_ + p0;

    #pragma unroll 1
    for (int c0 = 0; c0 < FD; c0 += KC) {
        if (c0) __syncthreads();
        load_plane(g_wch, FD, c0, sBh, t);
        load_plane(g_wcl, FD, c0, sBl, t);
        #pragma unroll
        for (int k = 0; k < 32; k++) {
            int idx = k * 256 + t;
            int c = idx >> 7, p = idx & 127;       // consecutive t -> consecutive p
            float x = fmaxf(fmaf(fb[(size_t)(c0 + c) * P_ + p], g_bns[c0+c], g_bnt[c0+c]), 0.f);
            split2(x, sAh[p*TPAD + c], sAl[p*TPAD + c]);
        }
        cpa_commit_wait();
        __syncthreads();
        gemm64(acc, sAh, sAl, sBh, sBl, wm, wn, lane);
    }

    float* dst = g_val + ((size_t)bn * P_ + p0) * DIM;
    int r0 = wm + (lane >> 2);
    int c0 = wn + (lane & 3) * 2;
    #pragma unroll
    for (int mt = 0; mt < 4; mt++)
        #pragma unroll
        for (int nt = 0; nt < 4; nt++) {
            int row = r0 + mt*16, col = c0 + nt*8;
            *(float2*)&dst[(size_t)row*DIM + col]     = make_float2(acc[mt][nt][0], acc[mt][nt][1]);
            *(float2*)&dst[(size_t)(row+8)*DIM + col] = make_float2(acc[mt][nt][2], acc[mt][nt][3]);
        }
}

// ---------------- K2: uv + bilinear + attention + residual + LN1 ----------------
__global__ void __launch_bounds__(256) k_attn(const float* __restrict__ ln1g,
                                              const float* __restrict__ ln1b) {
    __shared__ float sHm[BNV*9];
    int t = threadIdx.x;
    if (t < BNV*9) sHm[t] = g_Hm[t];
    __syncthreads();

    int warp = t >> 5, lane = t & 31;
    int pix = blockIdx.x * 8 + warp;
    int b = pix / P_;
    int p = pix - b * P_;
    int x = p % W_, y = p / W_;
    float px = ((float)x / (float)(W_-1)) * IMG_W_;
    float py = ((float)y / (float)(H_-1)) * IMG_H_;
    int d0 = lane << 2;

    const float4 q4 = *(const float4*)&g_val[((size_t)(b*N_)*P_ + p) * DIM + d0];
    float qs = q4.x*q4.x + q4.y*q4.y + q4.z*q4.z + q4.w*q4.w;

    // per-view gather + weighted sum; NO shuffles inside the loop so loads pipeline
    float vb[N_][4];
    float ssv[N_], ddv[N_], valid[N_];
    #pragma unroll
    for (int n = 0; n < N_; n++) {
        int bn = b*N_ + n;
        const float* Hm = &sHm[bn*9];
        float hx = Hm[0]*px + Hm[1]*py + Hm[2];
        float hy = Hm[3]*px + Hm[4]*py + Hm[5];
        float hz = Hm[6]*px + Hm[7]*py + Hm[8];
        float ux = ((hx / hz) / IMG_W_) * (float)W_;
        float uy = ((hy / hz) / IMG_H_) * (float)H_;
        float fx = floorf(ux), fy = floorf(uy);
        float wx = ux - fx,  wy = uy - fy;
        valid[n] = (ux >= 0.f && ux <= (float)(W_-1) &&
                    uy >= 0.f && uy <= (float)(H_-1)) ? 1.0f : 0.0f;
        int x0 = min(max((int)fx, 0), W_-1);
        int x1 = min(x0+1, W_-1);
        int y0 = min(max((int)fy, 0), H_-1);
        int y1 = min(y0+1, H_-1);
        float w00 = (1.f-wx)*(1.f-wy), w01 = wx*(1.f-wy);
        float w10 = (1.f-wx)*wy,       w11 = wx*wy;
        const float* base = &g_val[(size_t)bn*P_*DIM + d0];
        float4 a00 = *(const float4*)&base[(size_t)(y0*W_+x0)*DIM];
        float4 a01 = *(const float4*)&base[(size_t)(y0*W_+x1)*DIM];
        float4 a10 = *(const float4*)&base[(size_t)(y1*W_+x0)*DIM];
        float4 a11 = *(const float4*)&base[(size_t)(y1*W_+x1)*DIM];
        float v0 = a00.x*w00 + a01.x*w01 + a10.x*w10 + a11.x*w11;
        float v1 = a00.y*w00 + a01.y*w01 + a10.y*w10 + a11.y*w11;
        float v2 = a00.z*w00 + a01.z*w01 + a10.z*w10 + a11.z*w11;
        float v3 = a00.w*w00 + a01.w*w01 + a10.w*w10 + a11.w*w11;
        vb[n][0] = v0; vb[n][1] = v1; vb[n][2] = v2; vb[n][3] = v3;
        ssv[n] = v0*v0 + v1*v1 + v2*v2 + v3*v3;
        ddv[n] = q4.x*v0 + q4.y*v1 + q4.z*v2 + q4.w*v3;
    }
    // 13 independent reduction chains -> good shuffle ILP
    qs = wsum(qs);
    #pragma unroll
    for (int n = 0; n < N_; n++) { ssv[n] = wsum(ssv[n]); ddv[n] = wsum(ddv[n]); }
    float qinv = 1.0f / fmaxf(sqrtf(qs), 1e-12f);
    float dot[N_];
    #pragma unroll
    for (int n = 0; n < N_; n++)
        dot[n] = ddv[n] * qinv * (1.0f / fmaxf(sqrtf(ssv[n]), 1e-12f)) * valid[n];

    float m = dot[0];
    #pragma unroll
    for (int n = 1; n < N_; n++) m = fmaxf(m, dot[n]);
    float e[N_], s = 0.f;
    #pragma unroll
    for (int n = 0; n < N_; n++) { e[n] = expf(dot[n] - m); s += e[n]; }
    float sinv = 1.0f / s;
    float z[4] = {q4.x, q4.y, q4.z, q4.w};
    #pragma unroll
    for (int n = 0; n < N_; n++) {
        float a = e[n] * sinv;
        #pragma unroll
        for (int i = 0; i < 4; i++) z[i] = fmaf(a, vb[n][i], z[i]);
    }
    float ls = z[0] + z[1] + z[2] + z[3];
    ls = wsum(ls);
    float mean = ls * (1.0f / DIM);
    float vv = 0.f;
    #pragma unroll
    for (int i = 0; i < 4; i++) { float d = z[i] - mean; vv += d*d; }
    vv = wsum(vv);
    float rstd = 1.0f / sqrtf(vv * (1.0f / DIM) + 1e-5f);
    float4 g4 = *(const float4*)&ln1g[d0];
    float4 b4 = *(const float4*)&ln1b[d0];
    float zn[4];
    zn[0] = (z[0]-mean)*rstd*g4.x + b4.x;
    zn[1] = (z[1]-mean)*rstd*g4.y + b4.y;
    zn[2] = (z[2]-mean)*rstd*g4.z + b4.z;
    zn[3] = (z[3]-mean)*rstd*g4.w + b4.w;
    *(float4*)&g_zln[(size_t)pix*DIM + d0] = make_float4(zn[0], zn[1], zn[2], zn[3]);
    __nv_bfloat16 h0,l0,h1,l1,h2,l2,h3,l3;
    split2(zn[0], h0, l0); split2(zn[1], h1, l1);
    split2(zn[2], h2, l2); split2(zn[3], h3, l3);
    *(uint2*)&g_zh[(size_t)pix*DIM + d0] = make_uint2(pack2(h0,h1), pack2(h2,h3));
    *(uint2*)&g_zl[(size_t)pix*DIM + d0] = make_uint2(pack2(l0,l1), pack2(l2,l3));
}

// ---------------- K3: MLP1 (HMMA, chunked) + bias + exact GELU + split store ----------------
__global__ void __launch_bounds__(256, 2) k_mlp1_tc(const float* __restrict__ b1) {
    extern __shared__ __nv_bfloat16 smb[];
    __nv_bfloat16* sAh = smb;
    __nv_bfloat16* sAl = smb + TILE_ELE;
    __nv_bfloat16* sBh = smb + 2*TILE_ELE;
    __nv_bfloat16* sBl = smb + 3*TILE_ELE;
    int t = threadIdx.x, wid = t >> 5, lane = t & 31;
    int t0 = blockIdx.x * 128;
    int j0 = blockIdx.y * 128;

    float acc[4][4][4] = {};
    int wm = (wid >> 2) * 64, wn = (wid & 3) * 32;

    #pragma unroll 1
    for (int c0 = 0; c0 < DIM; c0 += KC) {
        if (c0) __syncthreads();
        load_plane(g_zh + (size_t)t0*DIM, DIM, c0, sAh, t);
        load_plane(g_zl + (size_t)t0*DIM, DIM, c0, sAl, t);
        load_plane(g_w1h + (size_t)j0*DIM, DIM, c0, sBh, t);
        load_plane(g_w1l + (size_t)j0*DIM, DIM, c0, sBl, t);
        cpa_commit_wait();
        __syncthreads();
        gemm64(acc, sAh, sAl, sBh, sBl, wm, wn, lane);
    }

    int r0 = wm + (lane >> 2);
    int c0 = wn + (lane & 3) * 2;
    #pragma unroll
    for (int mt = 0; mt < 4; mt++)
        #pragma unroll
        for (int nt = 0; nt < 4; nt++) {
            int row = r0 + mt*16, col = c0 + nt*8;
            float bj0 = b1[j0 + col], bj1 = b1[j0 + col + 1];
            float v00 = gelu_exact(acc[mt][nt][0] + bj0);
            float v01 = gelu_exact(acc[mt][nt][1] + bj1);
            float v10 = gelu_exact(acc[mt][nt][2] + bj0);
            float v11 = gelu_exact(acc[mt][nt][3] + bj1);
            __nv_bfloat16 ha,la,hb,lb;
            size_t o0 = (size_t)(t0+row)*(2*DIM) + j0 + col;
            size_t o1 = (size_t)(t0+row+8)*(2*DIM) + j0 + col;
            split2(v00, ha, la); split2(v01, hb, lb);
            *(uint32_t*)&g_hh[o0] = pack2(ha, hb);
            *(uint32_t*)&g_hl[o0] = pack2(la, lb);
            split2(v10, ha, la); split2(v11, hb, lb);
            *(uint32_t*)&g_hh[o1] = pack2(ha, hb);
            *(uint32_t*)&g_hl[o1] = pack2(la, lb);
        }
}

// ---------------- K4: MLP2 (HMMA, K=256 chunked) + residual + LN2 + transposed out ----------------
__global__ void __launch_bounds__(256, 2) k_mlp2_tc(const float* __restrict__ b2,
                                                    const float* __restrict__ g2,
                                                    const float* __restrict__ bb2,
                                                    float* __restrict__ out) {
    extern __shared__ __nv_bfloat16 smb[];
    __nv_bfloat16* sAh = smb;
    __nv_bfloat16* sAl = smb + TILE_ELE;
    __nv_bfloat16* sBh = smb + 2*TILE_ELE;
    __nv_bfloat16* sBl = smb + 3*TILE_ELE;
    int t = threadIdx.x, wid = t >> 5, lane = t & 31;
    int t0 = blockIdx.x * 128;

    float acc[4][4][4] = {};
    int wm = (wid >> 2) * 64, wn = (wid & 3) * 32;

    #pragma unroll 1
    for (int c0 = 0; c0 < 2*DIM; c0 += KC) {
        if (c0) __syncthreads();
        load_plane(g_hh + (size_t)t0*(2*DIM), 2*DIM, c0, sAh, t);
        load_plane(g_hl + (size_t)t0*(2*DIM), 2*DIM, c0, sAl, t);
        load_plane(g_w2h, 2*DIM, c0, sBh, t);
        load_plane(g_w2l, 2*DIM, c0, sBl, t);
        cpa_commit_wait();
        __syncthreads();
        gemm64(acc, sAh, sAl, sBh, sBl, wm, wn, lane);
    }
    __syncthreads();   // smem reuse below

    float* smT   = (float*)smb;             // [128][129] fp32
    float* sMean = smT + 128*129;
    float* sRstd = sMean + 128;
    const float* zb = g_zln + (size_t)t0 * DIM;
    int r0 = wm + (lane >> 2);
    int c0 = wn + (lane & 3) * 2;
    #pragma unroll
    for (int mt = 0; mt < 4; mt++)
        #pragma unroll
        for (int nt = 0; nt < 4; nt++) {
            int row = r0 + mt*16, col = c0 + nt*8;
            float b20 = b2[col], b21 = b2[col+1];
            float2 z0 = *(const float2*)&zb[(size_t)row*DIM + col];
            float2 z1 = *(const float2*)&zb[(size_t)(row+8)*DIM + col];
            smT[row*129 + col]       = acc[mt][nt][0] + b20 + z0.x;
            smT[row*129 + col + 1]   = acc[mt][nt][1] + b21 + z0.y;
            smT[(row+8)*129 + col]   = acc[mt][nt][2] + b20 + z1.x;
            smT[(row+8)*129 + col+1] = acc[mt][nt][3] + b21 + z1.y;
        }
    __syncthreads();
    if (t < 128) {
        float s = 0.f, q = 0.f;
        #pragma unroll 8
        for (int c = 0; c < 128; c++) {
            float v = smT[t*129 + c];
            s += v; q += v*v;
        }
        float mean = s * (1.0f / DIM);
        float var  = fmaxf(q * (1.0f / DIM) - mean*mean, 0.0f);
        sMean[t] = mean;
        sRstd[t] = 1.0f / sqrtf(var + 1e-5f);
    }
    __syncthreads();
    int b = t0 / P_;
    int prem = t0 - b * P_;
    #pragma unroll 4
    for (int k = 0; k < 64; k++) {
        int idx = k * 256 + t;
        int d = idx >> 7, p = idx & 127;      // consecutive t -> consecutive p
        float v = smT[p*129 + d];
        out[((size_t)(b*DIM + d))*P_ + prem + p] =
            (v - sMean[p]) * sRstd[p] * g2[d] + bb2[d];
    }
}

// ---------------- launch ----------------
extern "C" void kernel_launch(void* const* d_in, const int* in_sizes, int n_in,
                              void* d_out, int out_size) {
    const float* feature   = (const float*)d_in[0];
    const float* I_src     = (const float*)d_in[1];
    const float* I_tar_inv = (const float*)d_in[2];
    const float* E         = (const float*)d_in[3];
    const float* dis       = (const float*)d_in[4];
    const float* nrm       = (const float*)d_in[5];
    const float* conv_w    = (const float*)d_in[6];
    const float* bn_gamma  = (const float*)d_in[7];
    const float* bn_beta   = (const float*)d_in[8];
    const float* bn_mean   = (const float*)d_in[9];
    const float* bn_var    = (const float*)d_in[10];
    const float* ln1_g     = (const float*)d_in[11];
    const float* ln1_b     = (const float*)d_in[12];
    const float* ln2_g     = (const float*)d_in[13];
    const float* ln2_b     = (const float*)d_in[14];
    const float* mlp_w1    = (const float*)d_in[15];
    const float* mlp_b1    = (const float*)d_in[16];
    const float* mlp_w2    = (const float*)d_in[17];
    const float* mlp_b2    = (const float*)d_in[18];
    float* out = (float*)d_out;

    cudaFuncSetAttribute(k_conv_tc, cudaFuncAttributeMaxDynamicSharedMemorySize, SMEM_BYTES);
    cudaFuncSetAttribute(k_mlp1_tc, cudaFuncAttributeMaxDynamicSharedMemorySize, SMEM_BYTES);
    cudaFuncSetAttribute(k_mlp2_tc, cudaFuncAttributeMaxDynamicSharedMemorySize, SMEM_BYTES);

    k_setup<<<48, 256>>>(I_src, I_tar_inv, E, dis, nrm, conv_w,
                         bn_gamma, bn_beta, bn_mean, bn_var, mlp_w1, mlp_w2);
    k_conv_tc<<<dim3(P_/128, BNV), 256, SMEM_BYTES>>>(feature);
    k_attn<<<T2/8, 256>>>(ln1_g, ln1_b);
    k_mlp1_tc<<<dim3(T2/128, 2), 256, SMEM_BYTES>>>(mlp_b1);
    k_mlp2_tc<<<T2/128, 256, SMEM_BYTES>>>(mlp_b2, ln2_g, ln2_b, out);
}

// round 8
// speedup vs baseline: 1.7287x; 1.0206x over previous
#include <cuda_runtime.h>
#include <cuda_bf16.h>
#include <math.h>
#include <stdint.h>

#define B_    2
#define N_    6
#define FD    128
#define DIM   128
#define H_    64
#define W_    176
#define P_    (H_*W_)          // 11264
#define BNV   (B_*N_)          // 12
#define T2    (B_*P_)          // 22528
#define IMG_W_ 704.0f
#define IMG_H_ 256.0f

// chunk tile: 128 rows x 32 bf16 cols, padded to 40 (80 B row stride, 16B aligned)
#define KC        32
#define TPAD      40
#define TROWB     80
#define PLANE_ELE (128*TPAD)             // 5120 bf16
#define STAGE_ELE (4*PLANE_ELE)          // Ah, Al, Bh, Bl
#define SMEM_BYTES (2*STAGE_ELE*2)       // 81920 B, 2-stage ring

// ---------------- scratch ----------------
__device__ float         g_Hm[BNV*9];
__device__ float         g_bns[FD];
__device__ float         g_bnt[FD];
__device__ __nv_bfloat16 g_wch[DIM*FD],        g_wcl[DIM*FD];         // conv W [o][c]
__device__ __nv_bfloat16 g_w1h[(2*DIM)*DIM],   g_w1l[(2*DIM)*DIM];    // w1^T [j][c]
__device__ __nv_bfloat16 g_w2h[DIM*(2*DIM)],   g_w2l[DIM*(2*DIM)];    // w2^T [d][j]
__device__ float         g_val[(size_t)BNV*P_*DIM];                    // conv out [bn][p][d]
__device__ float         g_zln[(size_t)T2*DIM];                        // post-LN1 fp32
__device__ __nv_bfloat16 g_zh[(size_t)T2*DIM], g_zl[(size_t)T2*DIM];  // post-LN1 split
__device__ __nv_bfloat16 g_hh[(size_t)T2*(2*DIM)], g_hl[(size_t)T2*(2*DIM)]; // hidden split

// ---------------- helpers ----------------
__device__ __forceinline__ float wsum(float v) {
    #pragma unroll
    for (int o = 16; o > 0; o >>= 1) v += __shfl_xor_sync(0xFFFFFFFFu, v, o);
    return v;
}
__device__ __forceinline__ float gelu_exact(float x) {
    return 0.5f * x * (1.0f + erff(x * 0.70710678118654752f));
}
__device__ __forceinline__ void split2(float x, __nv_bfloat16& h, __nv_bfloat16& l) {
    h = __float2bfloat16(x);
    l = __float2bfloat16(x - __bfloat162float(h));
}
__device__ __forceinline__ uint32_t pack2(__nv_bfloat16 a, __nv_bfloat16 b) {
    return (uint32_t)__bfloat16_as_ushort(a) | ((uint32_t)__bfloat16_as_ushort(b) << 16);
}

// ---------------- async copy ----------------
__device__ __forceinline__ void cpa16(uint32_t s, const void* g) {
    asm volatile("cp.async.cg.shared.global [%0], [%1], 16;" :: "r"(s), "l"(g));
}
__device__ __forceinline__ void cpa_commit() { asm volatile("cp.async.commit_group;"); }
__device__ __forceinline__ void cpa_wait0()  { asm volatile("cp.async.wait_group 0;"); }

// one 128x32 chunk of a row-major bf16 plane -> padded smem tile (2x cp.async16/thread)
__device__ __forceinline__ void load_plane32(const __nv_bfloat16* g, int rstride, int c0,
                                             __nv_bfloat16* sm, int t) {
    uint32_t sb = (uint32_t)__cvta_generic_to_shared(sm);
    #pragma unroll
    for (int k = 0; k < 2; k++) {
        int i = k * 256 + t;
        int row = i >> 2, seg = i & 3;
        cpa16(sb + row*TROWB + seg*16, g + (size_t)row*rstride + c0 + seg*8);
    }
}

// ---------------- warp-mma primitives ----------------
__device__ __forceinline__ void ldsm4(uint32_t* r, uint32_t addr) {
    asm volatile("ldmatrix.sync.aligned.m8n8.x4.shared.b16 {%0,%1,%2,%3}, [%4];"
        : "=r"(r[0]), "=r"(r[1]), "=r"(r[2]), "=r"(r[3]) : "r"(addr));
}
__device__ __forceinline__ void ldsm2(uint32_t* r, uint32_t addr) {
    asm volatile("ldmatrix.sync.aligned.m8n8.x2.shared.b16 {%0,%1}, [%2];"
        : "=r"(r[0]), "=r"(r[1]) : "r"(addr));
}
__device__ __forceinline__ void mma_bf16(float* d, const uint32_t* a, const uint32_t* b) {
    asm volatile("mma.sync.aligned.m16n8k16.row.col.f32.bf16.bf16.f32 "
        "{%0,%1,%2,%3}, {%4,%5,%6,%7}, {%8,%9}, {%0,%1,%2,%3};"
        : "+f"(d[0]), "+f"(d[1]), "+f"(d[2]), "+f"(d[3])
        : "r"(a[0]), "r"(a[1]), "r"(a[2]), "r"(a[3]), "r"(b[0]), "r"(b[1]));
}

// one K=32 chunk: acc += A(128x32) * B^T(128x32), 3-term bf16 split
__device__ __forceinline__ void gemm32(float acc[4][4][4], const __nv_bfloat16* stage,
                                       int wm, int wn, int lane) {
    uint32_t base = (uint32_t)__cvta_generic_to_shared(stage);
    uint32_t aH = base;
    uint32_t aL = base + PLANE_ELE*2;
    uint32_t bH = base + 2*PLANE_ELE*2;
    uint32_t bL = base + 3*PLANE_ELE*2;
    uint32_t aoff = (uint32_t)(wm + (lane & 15)) * TROWB + ((lane >> 4) << 4);
    uint32_t boff = (uint32_t)(wn + (lane & 7))  * TROWB + (((lane >> 3) & 1) << 4);
    #pragma unroll
    for (int kk = 0; kk < 2; kk++) {
        uint32_t kb = (uint32_t)kk * 32;
        uint32_t ah[4][4], al[4][4], bh[4][2], bl[4][2];
        #pragma unroll
        for (int mt = 0; mt < 4; mt++) {
            uint32_t o = aoff + (uint32_t)mt * 16 * TROWB + kb;
            ldsm4(ah[mt], aH + o);
            ldsm4(al[mt], aL + o);
        }
        #pragma unroll
        for (int nt = 0; nt < 4; nt++) {
            uint32_t o = boff + (uint32_t)nt * 8 * TROWB + kb;
            ldsm2(bh[nt], bH + o);
            ldsm2(bl[nt], bL + o);
        }
        #pragma unroll
        for (int mt = 0; mt < 4; mt++)
            #pragma unroll
            for (int nt = 0; nt < 4; nt++) {
                mma_bf16(acc[mt][nt], ah[mt], bh[nt]);
                mma_bf16(acc[mt][nt], ah[mt], bl[nt]);
                mma_bf16(acc[mt][nt], al[mt], bh[nt]);
            }
    }
}

// ---------------- K0: setup ----------------
__global__ void k_setup(const float* __restrict__ I_src, const float* __restrict__ I_tar_inv,
                        const float* __restrict__ E, const float* __restrict__ dis,
                        const float* __restrict__ nrm, const float* __restrict__ conv_w,
                        const float* __restrict__ bg, const float* __restrict__ bb,
                        const float* __restrict__ bm, const float* __restrict__ bv,
                        const float* __restrict__ w1, const float* __restrict__ w2) {
    int t = threadIdx.x;
    if (blockIdx.x == 0) {
        if (t < BNV) {
            int b = t / N_;
            float ds = dis[b];
            float M[9], A[9];
            #pragma unroll
            for (int i = 0; i < 3; i++) {
                float Ti = E[t*16 + i*4 + 3];
                #pragma unroll
                for (int j = 0; j < 3; j++)
                    M[i*3+j] = E[t*16 + i*4 + j] - Ti * nrm[b*3+j] / ds;
            }
            #pragma unroll
            for (int i = 0; i < 3; i++)
                #pragma unroll
                for (int j = 0; j < 3; j++) {
                    float s = 0.f;
                    #pragma unroll
                    for (int k = 0; k < 3; k++) s += I_src[t*9 + i*3 + k] * M[k*3+j];
                    A[i*3+j] = s;
                }
            #pragma unroll
            for (int i = 0; i < 3; i++)
                #pragma unroll
                for (int j = 0; j < 3; j++) {
                    float s = 0.f;
                    #pragma unroll
                    for (int k = 0; k < 3; k++) s += A[i*3+k] * I_tar_inv[b*9 + k*3 + j];
                    g_Hm[t*9 + i*3 + j] = s;
                }
        }
        if (t < FD) {
            float s = bg[t] / sqrtf(bv[t] + 1e-5f);
            g_bns[t] = s;
            g_bnt[t] = bb[t] - bm[t] * s;
        }
    }
    int g = blockIdx.x * blockDim.x + t;
    int stride = gridDim.x * blockDim.x;
    for (int i = g; i < DIM*FD; i += stride)
        split2(conv_w[i], g_wch[i], g_wcl[i]);               // already [o][c]
    for (int i = g; i < (2*DIM)*DIM; i += stride) {
        int j = i >> 7, c = i & 127;
        split2(w1[c*(2*DIM) + j], g_w1h[i], g_w1l[i]);       // -> [j][c]
    }
    for (int i = g; i < DIM*(2*DIM); i += stride) {
        int d = i >> 8, j = i & 255;
        split2(w2[j*DIM + d], g_w2h[i], g_w2l[i]);           // -> [d][j]
    }
}

// ---------------- K1: conv GEMM (HMMA, pipelined; A reg-staged, B cp.async) ----------------
__global__ void __launch_bounds__(256, 2) k_conv_tc(const float* __restrict__ feat) {
    extern __shared__ __nv_bfloat16 smb[];
    __nv_bfloat16* stage[2] = { smb, smb + STAGE_ELE };
    int t = threadIdx.x, wid = t >> 5, lane = t & 31;
    int bn = blockIdx.y;
    int p0 = blockIdx.x * 128;

    float acc[4][4][4] = {};
    int wm = (wid >> 2) * 64, wn = (wid & 3) * 32;
    const float* fb = feat + (size_t)bn * FD * P_ + p0;
    int ap = t & 127;                // this thread's pixel
    int acb = (t >> 7) * 16;         // this thread's 16-channel base within chunk

    // A prefetch: 16 consecutive channels at fixed pixel, BN+ReLU applied at load
    float rA[16];
    #pragma unroll
    for (int k = 0; k < 16; k++) {
        int c = acb + k;
        rA[k] = fmaxf(fmaf(fb[(size_t)c * P_ + ap], g_bns[c], g_bnt[c]), 0.f);
    }
    load_plane32(g_wch, FD, 0, stage[0] + 2*PLANE_ELE, t);
    load_plane32(g_wcl, FD, 0, stage[0] + 3*PLANE_ELE, t);
    cpa_commit();

    #pragma unroll 1
    for (int i = 0; i < 4; i++) {
        cpa_wait0();                              // B(i) landed
        // STS A(i): packed 32-bit stores of split pairs
        {
            __nv_bfloat16* sAh = stage[i & 1];
            __nv_bfloat16* sAl = stage[i & 1] + PLANE_ELE;
            #pragma unroll
            for (int j = 0; j < 8; j++) {
                __nv_bfloat16 h0, l0, h1, l1;
                split2(rA[2*j],   h0, l0);
                split2(rA[2*j+1], h1, l1);
                *(uint32_t*)&sAh[ap*TPAD + acb + 2*j] = pack2(h0, h1);
                *(uint32_t*)&sAl[ap*TPAD + acb + 2*j] = pack2(l0, l1);
            }
        }
        if (i < 3) {                              // A(i+1) -> regs
            int c0n = (i + 1) * KC;
            #pragma unroll
            for (int k = 0; k < 16; k++) {
                int c = c0n + acb + k;
                rA[k] = fmaxf(fmaf(fb[(size_t)c * P_ + ap], g_bns[c], g_bnt[c]), 0.f);
            }
        }
        __syncthreads();                          // A(i)+B(i) visible; gemm(i-1) drained
        if (i < 3) {                              // B(i+1) cp.async, overlaps gemm(i)
            int c0n = (i + 1) * KC;
            load_plane32(g_wch, FD, c0n, stage[(i+1) & 1] + 2*PLANE_ELE, t);
            load_plane32(g_wcl, FD, c0n, stage[(i+1) & 1] + 3*PLANE_ELE, t);
            cpa_commit();
        }
        gemm32(acc, stage[i & 1], wm, wn, lane);
    }

    float* dst = g_val + ((size_t)bn * P_ + p0) * DIM;
    int r0 = wm + (lane >> 2);
    int c0 = wn + (lane & 3) * 2;
    #pragma unroll
    for (int mt = 0; mt < 4; mt++)
        #pragma unroll
        for (int nt = 0; nt < 4; nt++) {
            int row = r0 + mt*16, col = c0 + nt*8;
            *(float2*)&dst[(size_t)row*DIM + col]     = make_float2(acc[mt][nt][0], acc[mt][nt][1]);
            *(float2*)&dst[(size_t)(row+8)*DIM + col] = make_float2(acc[mt][nt][2], acc[mt][nt][3]);
        }
}

// ---------------- K2: uv + bilinear + attention + residual + LN1 ----------------
__global__ void __launch_bounds__(256) k_attn(const float* __restrict__ ln1g,
                                              const float* __restrict__ ln1b) {
    __shared__ float sHm[BNV*9];
    int t = threadIdx.x;
    if (t < BNV*9) sHm[t] = g_Hm[t];
    __syncthreads();

    int warp = t >> 5, lane = t & 31;
    int pix = blockIdx.x * 8 + warp;
    int b = pix / P_;
    int p = pix - b * P_;
    int x = p % W_, y = p / W_;
    float px = ((float)x / (float)(W_-1)) * IMG_W_;
    float py = ((float)y / (float)(H_-1)) * IMG_H_;
    int d0 = lane << 2;

    const float4 q4 = *(const float4*)&g_val[((size_t)(b*N_)*P_ + p) * DIM + d0];
    float qs = q4.x*q4.x + q4.y*q4.y + q4.z*q4.z + q4.w*q4.w;

    float vb[N_][4];
    float ssv[N_], ddv[N_], valid[N_];
    #pragma unroll
    for (int n = 0; n < N_; n++) {
        int bn = b*N_ + n;
        const float* Hm = &sHm[bn*9];
        float hx = Hm[0]*px + Hm[1]*py + Hm[2];
        float hy = Hm[3]*px + Hm[4]*py + Hm[5];
        float hz = Hm[6]*px + Hm[7]*py + Hm[8];
        float ux = ((hx / hz) / IMG_W_) * (float)W_;
        float uy = ((hy / hz) / IMG_H_) * (float)H_;
        float fx = floorf(ux), fy = floorf(uy);
        float wx = ux - fx,  wy = uy - fy;
        valid[n] = (ux >= 0.f && ux <= (float)(W_-1) &&
                    uy >= 0.f && uy <= (float)(H_-1)) ? 1.0f : 0.0f;
        int x0 = min(max((int)fx, 0), W_-1);
        int x1 = min(x0+1, W_-1);
        int y0 = min(max((int)fy, 0), H_-1);
        int y1 = min(y0+1, H_-1);
        float w00 = (1.f-wx)*(1.f-wy), w01 = wx*(1.f-wy);
        float w10 = (1.f-wx)*wy,       w11 = wx*wy;
        const float* base = &g_val[(size_t)bn*P_*DIM + d0];
        float4 a00 = *(const float4*)&base[(size_t)(y0*W_+x0)*DIM];
        float4 a01 = *(const float4*)&base[(size_t)(y0*W_+x1)*DIM];
        float4 a10 = *(const float4*)&base[(size_t)(y1*W_+x0)*DIM];
        float4 a11 = *(const float4*)&base[(size_t)(y1*W_+x1)*DIM];
        float v0 = a00.x*w00 + a01.x*w01 + a10.x*w10 + a11.x*w11;
        float v1 = a00.y*w00 + a01.y*w01 + a10.y*w10 + a11.y*w11;
        float v2 = a00.z*w00 + a01.z*w01 + a10.z*w10 + a11.z*w11;
        float v3 = a00.w*w00 + a01.w*w01 + a10.w*w10 + a11.w*w11;
        vb[n][0] = v0; vb[n][1] = v1; vb[n][2] = v2; vb[n][3] = v3;
        ssv[n] = v0*v0 + v1*v1 + v2*v2 + v3*v3;
        ddv[n] = q4.x*v0 + q4.y*v1 + q4.z*v2 + q4.w*v3;
    }
    qs = wsum(qs);
    #pragma unroll
    for (int n = 0; n < N_; n++) { ssv[n] = wsum(ssv[n]); ddv[n] = wsum(ddv[n]); }
    float qinv = 1.0f / fmaxf(sqrtf(qs), 1e-12f);
    float dot[N_];
    #pragma unroll
    for (int n = 0; n < N_; n++)
        dot[n] = ddv[n] * qinv * (1.0f / fmaxf(sqrtf(ssv[n]), 1e-12f)) * valid[n];

    float m = dot[0];
    #pragma unroll
    for (int n = 1; n < N_; n++) m = fmaxf(m, dot[n]);
    float e[N_], s = 0.f;
    #pragma unroll
    for (int n = 0; n < N_; n++) { e[n] = expf(dot[n] - m); s += e[n]; }
    float sinv = 1.0f / s;
    float z[4] = {q4.x, q4.y, q4.z, q4.w};
    #pragma unroll
    for (int n = 0; n < N_; n++) {
        float a = e[n] * sinv;
        #pragma unroll
        for (int i = 0; i < 4; i++) z[i] = fmaf(a, vb[n][i], z[i]);
    }
    float ls = z[0] + z[1] + z[2] + z[3];
    ls = wsum(ls);
    float mean = ls * (1.0f / DIM);
    float vv = 0.f;
    #pragma unroll
    for (int i = 0; i < 4; i++) { float d = z[i] - mean; vv += d*d; }
    vv = wsum(vv);
    float rstd = 1.0f / sqrtf(vv * (1.0f / DIM) + 1e-5f);
    float4 g4 = *(const float4*)&ln1g[d0];
    float4 b4 = *(const float4*)&ln1b[d0];
    float zn[4];
    zn[0] = (z[0]-mean)*rstd*g4.x + b4.x;
    zn[1] = (z[1]-mean)*rstd*g4.y + b4.y;
    zn[2] = (z[2]-mean)*rstd*g4.z + b4.z;
    zn[3] = (z[3]-mean)*rstd*g4.w + b4.w;
    *(float4*)&g_zln[(size_t)pix*DIM + d0] = make_float4(zn[0], zn[1], zn[2], zn[3]);
    __nv_bfloat16 h0,l0,h1,l1,h2,l2,h3,l3;
    split2(zn[0], h0, l0); split2(zn[1], h1, l1);
    split2(zn[2], h2, l2); split2(zn[3], h3, l3);
    *(uint2*)&g_zh[(size_t)pix*DIM + d0] = make_uint2(pack2(h0,h1), pack2(h2,h3));
    *(uint2*)&g_zl[(size_t)pix*DIM + d0] = make_uint2(pack2(l0,l1), pack2(l2,l3));
}

// ---------------- pipelined chunk loader for pre-split planes ----------------
__device__ __forceinline__ void load_chunk4(const __nv_bfloat16* ah, const __nv_bfloat16* al,
                                            int astride,
                                            const __nv_bfloat16* bh, const __nv_bfloat16* bl,
                                            int bstride, int c0,
                                            __nv_bfloat16* st, int t) {
    load_plane32(ah, astride, c0, st,               t);
    load_plane32(al, astride, c0, st +   PLANE_ELE, t);
    load_plane32(bh, bstride, c0, st + 2*PLANE_ELE, t);
    load_plane32(bl, bstride, c0, st + 3*PLANE_ELE, t);
    cpa_commit();
}

// ---------------- K3: MLP1 (HMMA, pipelined) + bias + exact GELU + split store ----------------
__global__ void __launch_bounds__(256, 2) k_mlp1_tc(const float* __restrict__ b1) {
    extern __shared__ __nv_bfloat16 smb[];
    __nv_bfloat16* stage[2] = { smb, smb + STAGE_ELE };
    int t = threadIdx.x, wid = t >> 5, lane = t & 31;
    int t0 = blockIdx.x * 128;
    int j0 = blockIdx.y * 128;

    float acc[4][4][4] = {};
    int wm = (wid >> 2) * 64, wn = (wid & 3) * 32;
    const __nv_bfloat16* Ah = g_zh + (size_t)t0 * DIM;
    const __nv_bfloat16* Al = g_zl + (size_t)t0 * DIM;
    const __nv_bfloat16* Bh = g_w1h + (size_t)j0 * DIM;
    const __nv_bfloat16* Bl = g_w1l + (size_t)j0 * DIM;

    load_chunk4(Ah, Al, DIM, Bh, Bl, DIM, 0, stage[0], t);
    #pragma unroll 1
    for (int i = 0; i < 4; i++) {
        cpa_wait0();
        __syncthreads();
        if (i < 3)
            load_chunk4(Ah, Al, DIM, Bh, Bl, DIM, (i+1)*KC, stage[(i+1) & 1], t);
        gemm32(acc, stage[i & 1], wm, wn, lane);
    }

    int r0 = wm + (lane >> 2);
    int c0 = wn + (lane & 3) * 2;
    #pragma unroll
    for (int mt = 0; mt < 4; mt++)
        #pragma unroll
        for (int nt = 0; nt < 4; nt++) {
            int row = r0 + mt*16, col = c0 + nt*8;
            float bj0 = b1[j0 + col], bj1 = b1[j0 + col + 1];
            float v00 = gelu_exact(acc[mt][nt][0] + bj0);
            float v01 = gelu_exact(acc[mt][nt][1] + bj1);
            float v10 = gelu_exact(acc[mt][nt][2] + bj0);
            float v11 = gelu_exact(acc[mt][nt][3] + bj1);
            __nv_bfloat16 ha,la,hb,lb;
            size_t o0 = (size_t)(t0+row)*(2*DIM) + j0 + col;
            size_t o1 = (size_t)(t0+row+8)*(2*DIM) + j0 + col;
            split2(v00, ha, la); split2(v01, hb, lb);
            *(uint32_t*)&g_hh[o0] = pack2(ha, hb);
            *(uint32_t*)&g_hl[o0] = pack2(la, lb);
            split2(v10, ha, la); split2(v11, hb, lb);
            *(uint32_t*)&g_hh[o1] = pack2(ha, hb);
            *(uint32_t*)&g_hl[o1] = pack2(la, lb);
        }
}

// ---------------- K4: MLP2 (HMMA, K=256 pipelined) + residual + LN2 + transposed out ----------------
__global__ void __launch_bounds__(256, 2) k_mlp2_tc(const float* __restrict__ b2,
                                                    const float* __restrict__ g2,
                                                    const float* __restrict__ bb2,
                                                    float* __restrict__ out) {
    extern __shared__ __nv_bfloat16 smb[];
    __nv_bfloat16* stage[2] = { smb, smb + STAGE_ELE };
    int t = threadIdx.x, wid = t >> 5, lane = t & 31;
    int t0 = blockIdx.x * 128;

    float acc[4][4][4] = {};
    int wm = (wid >> 2) * 64, wn = (wid & 3) * 32;
    const __nv_bfloat16* Ah = g_hh + (size_t)t0 * (2*DIM);
    const __nv_bfloat16* Al = g_hl + (size_t)t0 * (2*DIM);

    load_chunk4(Ah, Al, 2*DIM, g_w2h, g_w2l, 2*DIM, 0, stage[0], t);
    #pragma unroll 1
    for (int i = 0; i < 8; i++) {
        cpa_wait0();
        __syncthreads();
        if (i < 7)
            load_chunk4(Ah, Al, 2*DIM, g_w2h, g_w2l, 2*DIM, (i+1)*KC, stage[(i+1) & 1], t);
        gemm32(acc, stage[i & 1], wm, wn, lane);
    }
    __syncthreads();   // smem reuse below

    float* smT   = (float*)smb;             // [128][129] fp32 = 66048 B
    float* sMean = smT + 128*129;
    float* sRstd = sMean + 128;
    const float* zb = g_zln + (size_t)t0 * DIM;
    int r0 = wm + (lane >> 2);
    int c0 = wn + (lane & 3) * 2;
    #pragma unroll
    for (int mt = 0; mt < 4; mt++)
        #pragma unroll
        for (int nt = 0; nt < 4; nt++) {
            int row = r0 + mt*16, col = c0 + nt*8;
            float b20 = b2[col], b21 = b2[col+1];
            float2 z0 = *(const float2*)&zb[(size_t)row*DIM + col];
            float2 z1 = *(const float2*)&zb[(size_t)(row+8)*DIM + col];
            smT[row*129 + col]       = acc[mt][nt][0] + b20 + z0.x;
            smT[row*129 + col + 1]   = acc[mt][nt][1] + b21 + z0.y;
            smT[(row+8)*129 + col]   = acc[mt][nt][2] + b20 + z1.x;
            smT[(row+8)*129 + col+1] = acc[mt][nt][3] + b21 + z1.y;
        }
    __syncthreads();
    if (t < 128) {
        float s = 0.f, q = 0.f;
        #pragma unroll 8
        for (int c = 0; c < 128; c++) {
            float v = smT[t*129 + c];
            s += v; q += v*v;
        }
        float mean = s * (1.0f / DIM);
        float var  = fmaxf(q * (1.0f / DIM) - mean*mean, 0.0f);
        sMean[t] = mean;
        sRstd[t] = 1.0f / sqrtf(var + 1e-5f);
    }
    __syncthreads();
    int b = t0 / P_;
    int prem = t0 - b * P_;
    #pragma unroll 4
    for (int k = 0; k < 64; k++) {
        int idx = k * 256 + t;
        int d = idx >> 7, p = idx & 127;      // consecutive t -> consecutive p
        float v = smT[p*129 + d];
        out[((size_t)(b*DIM + d))*P_ + prem + p] =
            (v - sMean[p]) * sRstd[p] * g2[d] + bb2[d];
    }
}

// ---------------- launch ----------------
extern "C" void kernel_launch(void* const* d_in, const int* in_sizes, int n_in,
                              void* d_out, int out_size) {
    const float* feature   = (const float*)d_in[0];
    const float* I_src     = (const float*)d_in[1];
    const float* I_tar_inv = (const float*)d_in[2];
    const float* E         = (const float*)d_in[3];
    const float* dis       = (const float*)d_in[4];
    const float* nrm       = (const float*)d_in[5];
    const float* conv_w    = (const float*)d_in[6];
    const float* bn_gamma  = (const float*)d_in[7];
    const float* bn_beta   = (const float*)d_in[8];
    const float* bn_mean   = (const float*)d_in[9];
    const float* bn_var    = (const float*)d_in[10];
    const float* ln1_g     = (const float*)d_in[11];
    const float* ln1_b     = (const float*)d_in[12];
    const float* ln2_g     = (const float*)d_in[13];
    const float* ln2_b     = (const float*)d_in[14];
    const float* mlp_w1    = (const float*)d_in[15];
    const float* mlp_b1    = (const float*)d_in[16];
    const float* mlp_w2    = (const float*)d_in[17];
    const float* mlp_b2    = (const float*)d_in[18];
    float* out = (float*)d_out;

    cudaFuncSetAttribute(k_conv_tc, cudaFuncAttributeMaxDynamicSharedMemorySize, SMEM_BYTES);
    cudaFuncSetAttribute(k_mlp1_tc, cudaFuncAttributeMaxDynamicSharedMemorySize, SMEM_BYTES);
    cudaFuncSetAttribute(k_mlp2_tc, cudaFuncAttributeMaxDynamicSharedMemorySize, SMEM_BYTES);

    k_setup<<<48, 256>>>(I_src, I_tar_inv, E, dis, nrm, conv_w,
                         bn_gamma, bn_beta, bn_mean, bn_var, mlp_w1, mlp_w2);
    k_conv_tc<<<dim3(P_/128, BNV), 256, SMEM_BYTES>>>(feature);
    k_attn<<<T2/8, 256>>>(ln1_g, ln1_b);
    k_mlp1_tc<<<dim3(T2/128, 2), 256, SMEM_BYTES>>>(mlp_b1);
    k_mlp2_tc<<<T2/128, 256, SMEM_BYTES>>>(mlp_b2, ln2_g, ln2_b, out);
}

// round 10
// speedup vs baseline: 2.1208x; 1.2268x over previous
#include <cuda_runtime.h>
#include <cuda_fp16.h>
#include <math.h>
#include <stdint.h>

#define B_    2
#define N_    6
#define FD    128
#define DIM   128
#define H_    64
#define W_    176
#define P_    (H_*W_)          // 11264
#define BNV   (B_*N_)          // 12
#define T2    (B_*P_)          // 22528
#define IMG_W_ 704.0f
#define IMG_H_ 256.0f

// conv chunk tiles: 128 x 32 fp16, padded to 40 (80 B rows)
#define TPAD40   40
#define TROWB40  80
#define PLANE40  (128*TPAD40)
// mlp tiles: rows x 64 fp16, padded to 72 (144 B rows)
#define TPAD72   72
#define TROWB72  144

#define SMEM_CONV (2*3*PLANE40*2)            // 2 stages x (A,Bh,Bl) = 61440 B
#define SMEM_MLP1 ((128+64+64)*TPAD72*2)     // 36864 B
#define SMEM_MLP2 ((64+128+128)*TPAD72*2)    // 46080 B (gemm phase; epi needs 33.5KB)

// ---------------- scratch ----------------
__device__ float  g_Hm[BNV*9];
__device__ float  g_bns[FD];
__device__ float  g_bnt[FD];
__device__ __half g_wch[DIM*FD],      g_wcl[DIM*FD];       // conv W [o][c] split
__device__ __half g_w1h[(2*DIM)*DIM], g_w1l[(2*DIM)*DIM];  // w1^T [j][c] split
__device__ __half g_w2h[DIM*(2*DIM)], g_w2l[DIM*(2*DIM)];  // w2^T [d][j] split
__device__ float  g_val[(size_t)BNV*P_*DIM];               // conv out [bn][p][d] fp32
__device__ float  g_zln[(size_t)T2*DIM];                   // post-LN1 fp32 (residual)
__device__ __half g_zh[(size_t)T2*DIM];                    // post-LN1 fp16 (mlp1 A)
__device__ __half g_hh[(size_t)T2*(2*DIM)];                // hidden fp16 (mlp2 A)

// ---------------- helpers ----------------
__device__ __forceinline__ float wsum(float v) {
    #pragma unroll
    for (int o = 16; o > 0; o >>= 1) v += __shfl_xor_sync(0xFFFFFFFFu, v, o);
    return v;
}
__device__ __forceinline__ float gelu_exact(float x) {
    return 0.5f * x * (1.0f + erff(x * 0.70710678118654752f));
}
__device__ __forceinline__ uint32_t pack2h(__half a, __half b) {
    return (uint32_t)__half_as_ushort(a) | ((uint32_t)__half_as_ushort(b) << 16);
}

// ---------------- async copy ----------------
__device__ __forceinline__ void cpa16(uint32_t s, const void* g) {
    asm volatile("cp.async.cg.shared.global [%0], [%1], 16;" :: "r"(s), "l"(g));
}
__device__ __forceinline__ void cpa_commit() { asm volatile("cp.async.commit_group;"); }
__device__ __forceinline__ void cpa_wait0()  { asm volatile("cp.async.wait_group 0;"); }

// rows x 64 fp16 chunk of a row-major plane -> 144B-stride smem tile
__device__ __forceinline__ void load_rows72(const __half* g, int rstride, int c0,
                                            __half* sm, int rows, int t) {
    uint32_t sb = (uint32_t)__cvta_generic_to_shared(sm);
    for (int i = t; i < rows*8; i += 256) {
        int row = i >> 3, seg = i & 7;
        cpa16(sb + row*TROWB72 + seg*16, g + (size_t)row*rstride + c0 + seg*8);
    }
}
// 128 x 32 fp16 chunk -> 80B-stride smem tile
__device__ __forceinline__ void load_rows40(const __half* g, int rstride, int c0,
                                            __half* sm, int t) {
    uint32_t sb = (uint32_t)__cvta_generic_to_shared(sm);
    #pragma unroll
    for (int k = 0; k < 2; k++) {
        int i = k*256 + t;
        int row = i >> 2, seg = i & 3;
        cpa16(sb + row*TROWB40 + seg*16, g + (size_t)row*rstride + c0 + seg*8);
    }
}

// ---------------- warp-mma primitives ----------------
__device__ __forceinline__ void ldsm4(uint32_t* r, uint32_t addr) {
    asm volatile("ldmatrix.sync.aligned.m8n8.x4.shared.b16 {%0,%1,%2,%3}, [%4];"
        : "=r"(r[0]), "=r"(r[1]), "=r"(r[2]), "=r"(r[3]) : "r"(addr));
}
__device__ __forceinline__ void ldsm2(uint32_t* r, uint32_t addr) {
    asm volatile("ldmatrix.sync.aligned.m8n8.x2.shared.b16 {%0,%1}, [%2];"
        : "=r"(r[0]), "=r"(r[1]) : "r"(addr));
}
__device__ __forceinline__ void mma_f16(float* d, const uint32_t* a, const uint32_t* b) {
    asm volatile("mma.sync.aligned.m16n8k16.row.col.f32.f16.f16.f32 "
        "{%0,%1,%2,%3}, {%4,%5,%6,%7}, {%8,%9}, {%0,%1,%2,%3};"
        : "+f"(d[0]), "+f"(d[1]), "+f"(d[2]), "+f"(d[3])
        : "r"(a[0]), "r"(a[1]), "r"(a[2]), "r"(a[3]), "r"(b[0]), "r"(b[1]));
}

// K=32 chunk, warp tile 64x32 (conv): acc += A*(Bh^T+Bl^T)
__device__ __forceinline__ void gemm32_w64(float acc[4][4][4],
                                           const __half* sA, const __half* sBh,
                                           const __half* sBl, int wm, int wn, int lane) {
    uint32_t aB = (uint32_t)__cvta_generic_to_shared(sA);
    uint32_t bH = (uint32_t)__cvta_generic_to_shared(sBh);
    uint32_t bL = (uint32_t)__cvta_generic_to_shared(sBl);
    uint32_t aoff = (uint32_t)(wm + (lane & 15)) * TROWB40 + ((lane >> 4) << 4);
    uint32_t boff = (uint32_t)(wn + (lane & 7))  * TROWB40 + (((lane >> 3) & 1) << 4);
    #pragma unroll
    for (int kk = 0; kk < 2; kk++) {
        uint32_t kb = (uint32_t)kk * 32;
        uint32_t ah[4][4], bh[4][2], bl[4][2];
        #pragma unroll
        for (int mt = 0; mt < 4; mt++)
            ldsm4(ah[mt], aB + aoff + (uint32_t)mt*16*TROWB40 + kb);
        #pragma unroll
        for (int nt = 0; nt < 4; nt++) {
            uint32_t o = boff + (uint32_t)nt*8*TROWB40 + kb;
            ldsm2(bh[nt], bH + o);
            ldsm2(bl[nt], bL + o);
        }
        #pragma unroll
        for (int mt = 0; mt < 4; mt++)
            #pragma unroll
            for (int nt = 0; nt < 4; nt++) {
                mma_f16(acc[mt][nt], ah[mt], bh[nt]);
                mma_f16(acc[mt][nt], ah[mt], bl[nt]);
            }
    }
}

// K=64 chunk, warp tile 32x32 (mlp1/mlp2): acc += A*(Bh^T+Bl^T)
__device__ __forceinline__ void gemm64_w32(float acc[2][4][4],
                                           const __half* sA, const __half* sBh,
                                           const __half* sBl, int wm, int wn, int lane) {
    uint32_t aB = (uint32_t)__cvta_generic_to_shared(sA);
    uint32_t bH = (uint32_t)__cvta_generic_to_shared(sBh);
    uint32_t bL = (uint32_t)__cvta_generic_to_shared(sBl);
    uint32_t aoff = (uint32_t)(wm + (lane & 15)) * TROWB72 + ((lane >> 4) << 4);
    uint32_t boff = (uint32_t)(wn + (lane & 7))  * TROWB72 + (((lane >> 3) & 1) << 4);
    #pragma unroll
    for (int kk = 0; kk < 4; kk++) {
        uint32_t kb = (uint32_t)kk * 32;
        uint32_t ah[2][4], bh[4][2], bl[4][2];
        #pragma unroll
        for (int mt = 0; mt < 2; mt++)
            ldsm4(ah[mt], aB + aoff + (uint32_t)mt*16*TROWB72 + kb);
        #pragma unroll
        for (int nt = 0; nt < 4; nt++) {
            uint32_t o = boff + (uint32_t)nt*8*TROWB72 + kb;
            ldsm2(bh[nt], bH + o);
            ldsm2(bl[nt], bL + o);
        }
        #pragma unroll
        for (int mt = 0; mt < 2; mt++)
            #pragma unroll
            for (int nt = 0; nt < 4; nt++) {
                mma_f16(acc[mt][nt], ah[mt], bh[nt]);
                mma_f16(acc[mt][nt], ah[mt], bl[nt]);
            }
    }
}

// ---------------- K0: setup ----------------
__global__ void k_setup(const float* __restrict__ I_src, const float* __restrict__ I_tar_inv,
                        const float* __restrict__ E, const float* __restrict__ dis,
                        const float* __restrict__ nrm, const float* __restrict__ conv_w,
                        const float* __restrict__ bg, const float* __restrict__ bb,
                        const float* __restrict__ bm, const float* __restrict__ bv,
                        const float* __restrict__ w1, const float* __restrict__ w2) {
    int t = threadIdx.x;
    if (blockIdx.x == 0) {
        if (t < BNV) {
            int b = t / N_;
            float ds = dis[b];
            float M[9], A[9];
            #pragma unroll
            for (int i = 0; i < 3; i++) {
                float Ti = E[t*16 + i*4 + 3];
                #pragma unroll
                for (int j = 0; j < 3; j++)
                    M[i*3+j] = E[t*16 + i*4 + j] - Ti * nrm[b*3+j] / ds;
            }
            #pragma unroll
            for (int i = 0; i < 3; i++)
                #pragma unroll
                for (int j = 0; j < 3; j++) {
                    float s = 0.f;
                    #pragma unroll
                    for (int k = 0; k < 3; k++) s += I_src[t*9 + i*3 + k] * M[k*3+j];
                    A[i*3+j] = s;
                }
            #pragma unroll
            for (int i = 0; i < 3; i++)
                #pragma unroll
                for (int j = 0; j < 3; j++) {
                    float s = 0.f;
                    #pragma unroll
                    for (int k = 0; k < 3; k++) s += A[i*3+k] * I_tar_inv[b*9 + k*3 + j];
                    g_Hm[t*9 + i*3 + j] = s;
                }
        }
        if (t < FD) {
            float s = bg[t] / sqrtf(bv[t] + 1e-5f);
            g_bns[t] = s;
            g_bnt[t] = bb[t] - bm[t] * s;
        }
    }
    int g = blockIdx.x * blockDim.x + t;
    int stride = gridDim.x * blockDim.x;
    for (int i = g; i < DIM*FD; i += stride) {
        float w = conv_w[i];
        __half h = __float2half(w);
        g_wch[i] = h;
        g_wcl[i] = __float2half(w - __half2float(h));
    }
    for (int i = g; i < (2*DIM)*DIM; i += stride) {
        int j = i >> 7, c = i & 127;
        float w = w1[c*(2*DIM) + j];
        __half h = __float2half(w);
        g_w1h[i] = h;
        g_w1l[i] = __float2half(w - __half2float(h));
    }
    for (int i = g; i < DIM*(2*DIM); i += stride) {
        int d = i >> 8, j = i & 255;
        float w = w2[j*DIM + d];
        __half h = __float2half(w);
        g_w2h[i] = h;
        g_w2l[i] = __float2half(w - __half2float(h));
    }
}

// ---------------- K1: conv GEMM (A fp16 reg-staged, B split, pipelined) ----------------
__global__ void __launch_bounds__(256, 2) k_conv_tc(const float* __restrict__ feat) {
    extern __shared__ __half smh[];
    __half* stage[2] = { smh, smh + 3*PLANE40 };
    int t = threadIdx.x, wid = t >> 5, lane = t & 31;
    int bn = blockIdx.y;
    int p0 = blockIdx.x * 128;

    float acc[4][4][4] = {};
    int wm = (wid >> 2) * 64, wn = (wid & 3) * 32;
    const float* fb = feat + (size_t)bn * FD * P_ + p0;
    int ap  = t & 127;               // pixel
    int acb = (t >> 7) * 16;         // 16-channel base within chunk

    float rA[16];
    #pragma unroll
    for (int k = 0; k < 16; k++) {
        int c = acb + k;
        rA[k] = fmaxf(fmaf(fb[(size_t)c * P_ + ap], g_bns[c], g_bnt[c]), 0.f);
    }
    load_rows40(g_wch, FD, 0, stage[0] +   PLANE40, t);
    load_rows40(g_wcl, FD, 0, stage[0] + 2*PLANE40, t);
    cpa_commit();

    #pragma unroll 1
    for (int i = 0; i < 4; i++) {
        cpa_wait0();
        {
            __half* sA = stage[i & 1];
            #pragma unroll
            for (int j = 0; j < 8; j++)
                *(uint32_t*)&sA[ap*TPAD40 + acb + 2*j] =
                    pack2h(__float2half(rA[2*j]), __float2half(rA[2*j+1]));
        }
        if (i < 3) {
            int c0n = (i + 1) * 32;
            #pragma unroll
            for (int k = 0; k < 16; k++) {
                int c = c0n + acb + k;
                rA[k] = fmaxf(fmaf(fb[(size_t)c * P_ + ap], g_bns[c], g_bnt[c]), 0.f);
            }
        }
        __syncthreads();
        if (i < 3) {
            int c0n = (i + 1) * 32;
            load_rows40(g_wch, FD, c0n, stage[(i+1) & 1] +   PLANE40, t);
            load_rows40(g_wcl, FD, c0n, stage[(i+1) & 1] + 2*PLANE40, t);
            cpa_commit();
        }
        gemm32_w64(acc, stage[i & 1], stage[i & 1] + PLANE40, stage[i & 1] + 2*PLANE40,
                   wm, wn, lane);
    }

    float* dst = g_val + ((size_t)bn * P_ + p0) * DIM;
    int r0 = wm + (lane >> 2);
    int c0 = wn + (lane & 3) * 2;
    #pragma unroll
    for (int mt = 0; mt < 4; mt++)
        #pragma unroll
        for (int nt = 0; nt < 4; nt++) {
            int row = r0 + mt*16, col = c0 + nt*8;
            *(float2*)&dst[(size_t)row*DIM + col]     = make_float2(acc[mt][nt][0], acc[mt][nt][1]);
            *(float2*)&dst[(size_t)(row+8)*DIM + col] = make_float2(acc[mt][nt][2], acc[mt][nt][3]);
        }
}

// ---------------- K2: uv + bilinear + attention + residual + LN1 ----------------
__global__ void __launch_bounds__(256) k_attn(const float* __restrict__ ln1g,
                                              const float* __restrict__ ln1b) {
    __shared__ float sHm[BNV*9];
    int t = threadIdx.x;
    if (t < BNV*9) sHm[t] = g_Hm[t];
    __syncthreads();

    int warp = t >> 5, lane = t & 31;
    int pix = blockIdx.x * 8 + warp;
    int b = pix / P_;
    int p = pix - b * P_;
    int x = p % W_, y = p / W_;
    float px = ((float)x / (float)(W_-1)) * IMG_W_;
    float py = ((float)y / (float)(H_-1)) * IMG_H_;
    int d0 = lane << 2;

    const float4 q4 = *(const float4*)&g_val[((size_t)(b*N_)*P_ + p) * DIM + d0];
    float qs = q4.x*q4.x + q4.y*q4.y + q4.z*q4.z + q4.w*q4.w;

    float vb[N_][4];
    float ssv[N_], ddv[N_], valid[N_];
    #pragma unroll
    for (int n = 0; n < N_; n++) {
        int bn = b*N_ + n;
        const float* Hm = &sHm[bn*9];
        float hx = Hm[0]*px + Hm[1]*py + Hm[2];
        float hy = Hm[3]*px + Hm[4]*py + Hm[5];
        float hz = Hm[6]*px + Hm[7]*py + Hm[8];
        float ux = ((hx / hz) / IMG_W_) * (float)W_;
        float uy = ((hy / hz) / IMG_H_) * (float)H_;
        float fx = floorf(ux), fy = floorf(uy);
        float wx = ux - fx,  wy = uy - fy;
        valid[n] = (ux >= 0.f && ux <= (float)(W_-1) &&
                    uy >= 0.f && uy <= (float)(H_-1)) ? 1.0f : 0.0f;
        int x0 = min(max((int)fx, 0), W_-1);
        int x1 = min(x0+1, W_-1);
        int y0 = min(max((int)fy, 0), H_-1);
        int y1 = min(y0+1, H_-1);
        float w00 = (1.f-wx)*(1.f-wy), w01 = wx*(1.f-wy);
        float w10 = (1.f-wx)*wy,       w11 = wx*wy;
        const float* base = &g_val[(size_t)bn*P_*DIM + d0];
        float4 a00 = *(const float4*)&base[(size_t)(y0*W_+x0)*DIM];
        float4 a01 = *(const float4*)&base[(size_t)(y0*W_+x1)*DIM];
        float4 a10 = *(const float4*)&base[(size_t)(y1*W_+x0)*DIM];
        float4 a11 = *(const float4*)&base[(size_t)(y1*W_+x1)*DIM];
        float v0 = a00.x*w00 + a01.x*w01 + a10.x*w10 + a11.x*w11;
        float v1 = a00.y*w00 + a01.y*w01 + a10.y*w10 + a11.y*w11;
        float v2 = a00.z*w00 + a01.z*w01 + a10.z*w10 + a11.z*w11;
        float v3 = a00.w*w00 + a01.w*w01 + a10.w*w10 + a11.w*w11;
        vb[n][0] = v0; vb[n][1] = v1; vb[n][2] = v2; vb[n][3] = v3;
        ssv[n] = v0*v0 + v1*v1 + v2*v2 + v3*v3;
        ddv[n] = q4.x*v0 + q4.y*v1 + q4.z*v2 + q4.w*v3;
    }
    qs = wsum(qs);
    #pragma unroll
    for (int n = 0; n < N_; n++) { ssv[n] = wsum(ssv[n]); ddv[n] = wsum(ddv[n]); }
    float qinv = 1.0f / fmaxf(sqrtf(qs), 1e-12f);
    float dot[N_];
    #pragma unroll
    for (int n = 0; n < N_; n++)
        dot[n] = ddv[n] * qinv * (1.0f / fmaxf(sqrtf(ssv[n]), 1e-12f)) * valid[n];

    float m = dot[0];
    #pragma unroll
    for (int n = 1; n < N_; n++) m = fmaxf(m, dot[n]);
    float e[N_], s = 0.f;
    #pragma unroll
    for (int n = 0; n < N_; n++) { e[n] = expf(dot[n] - m); s += e[n]; }
    float sinv = 1.0f / s;
    float z[4] = {q4.x, q4.y, q4.z, q4.w};
    #pragma unroll
    for (int n = 0; n < N_; n++) {
        float a = e[n] * sinv;
        #pragma unroll
        for (int i = 0; i < 4; i++) z[i] = fmaf(a, vb[n][i], z[i]);
    }
    float ls = z[0] + z[1] + z[2] + z[3];
    ls = wsum(ls);
    float mean = ls * (1.0f / DIM);
    float vv = 0.f;
    #pragma unroll
    for (int i = 0; i < 4; i++) { float d = z[i] - mean; vv += d*d; }
    vv = wsum(vv);
    float rstd = 1.0f / sqrtf(vv * (1.0f / DIM) + 1e-5f);
    float4 g4 = *(const float4*)&ln1g[d0];
    float4 b4 = *(const float4*)&ln1b[d0];
    float zn[4];
    zn[0] = (z[0]-mean)*rstd*g4.x + b4.x;
    zn[1] = (z[1]-mean)*rstd*g4.y + b4.y;
    zn[2] = (z[2]-mean)*rstd*g4.z + b4.z;
    zn[3] = (z[3]-mean)*rstd*g4.w + b4.w;
    *(float4*)&g_zln[(size_t)pix*DIM + d0] = make_float4(zn[0], zn[1], zn[2], zn[3]);
    *(uint2*)&g_zh[(size_t)pix*DIM + d0] =
        make_uint2(pack2h(__float2half(zn[0]), __float2half(zn[1])),
                   pack2h(__float2half(zn[2]), __float2half(zn[3])));
}

// ---------------- K3: MLP1 (CTA 128tok x 64j, 3 CTAs/SM) ----------------
__global__ void __launch_bounds__(256, 3) k_mlp1_tc(const float* __restrict__ b1) {
    extern __shared__ __half smh[];
    __half* sA  = smh;                  // 128 x 72
    __half* sBh = smh + 128*TPAD72;     // 64 x 72
    __half* sBl = sBh + 64*TPAD72;      // 64 x 72
    int t = threadIdx.x, wid = t >> 5, lane = t & 31;
    int t0 = blockIdx.x * 128;
    int j0 = blockIdx.y * 64;

    float acc[2][4][4] = {};
    int wm = (wid >> 1) * 32;           // 4 m-groups over 128 tokens
    int wn = (wid & 1) * 32;            // 2 n-groups over 64 j
    const __half* Ag = g_zh + (size_t)t0 * DIM;
    const __half* Bh = g_w1h + (size_t)j0 * DIM;
    const __half* Bl = g_w1l + (size_t)j0 * DIM;

    #pragma unroll 1
    for (int c = 0; c < 2; c++) {
        if (c) __syncthreads();
        int c0 = c * 64;
        load_rows72(Ag, DIM, c0, sA, 128, t);
        load_rows72(Bh, DIM, c0, sBh, 64, t);
        load_rows72(Bl, DIM, c0, sBl, 64, t);
        cpa_commit();
        cpa_wait0();
        __syncthreads();
        gemm64_w32(acc, sA, sBh, sBl, wm, wn, lane);
    }

    int r0 = wm + (lane >> 2);
    int c0 = wn + (lane & 3) * 2;
    #pragma unroll
    for (int mt = 0; mt < 2; mt++)
        #pragma unroll
        for (int nt = 0; nt < 4; nt++) {
            int row = r0 + mt*16, col = c0 + nt*8;
            float bj0 = b1[j0 + col], bj1 = b1[j0 + col + 1];
            float v00 = gelu_exact(acc[mt][nt][0] + bj0);
            float v01 = gelu_exact(acc[mt][nt][1] + bj1);
            float v10 = gelu_exact(acc[mt][nt][2] + bj0);
            float v11 = gelu_exact(acc[mt][nt][3] + bj1);
            *(uint32_t*)&g_hh[(size_t)(t0+row)*(2*DIM) + j0 + col] =
                pack2h(__float2half(v00), __float2half(v01));
            *(uint32_t*)&g_hh[(size_t)(t0+row+8)*(2*DIM) + j0 + col] =
                pack2h(__float2half(v10), __float2half(v11));
        }
}

// ---------------- K4: MLP2 (CTA 64tok x 128d, 3 CTAs/SM) + residual + LN2 ----------------
__global__ void __launch_bounds__(256, 3) k_mlp2_tc(const float* __restrict__ b2,
                                                    const float* __restrict__ g2,
                                                    const float* __restrict__ bb2,
                                                    float* __restrict__ out) {
    extern __shared__ __half smh[];
    __half* sA  = smh;                  // 64 x 72
    __half* sBh = smh + 64*TPAD72;      // 128 x 72
    __half* sBl = sBh + 128*TPAD72;     // 128 x 72
    int t = threadIdx.x, wid = t >> 5, lane = t & 31;
    int t0 = blockIdx.x * 64;

    float acc[2][4][4] = {};
    int wm = (wid >> 2) * 32;           // 2 m-groups over 64 tokens
    int wn = (wid & 3) * 32;            // 4 n-groups over 128 d
    const __half* Ag = g_hh + (size_t)t0 * (2*DIM);

    #pragma unroll 1
    for (int c = 0; c < 4; c++) {
        if (c) __syncthreads();
        int c0 = c * 64;
        load_rows72(Ag,    2*DIM, c0, sA,   64, t);
        load_rows72(g_w2h, 2*DIM, c0, sBh, 128, t);
        load_rows72(g_w2l, 2*DIM, c0, sBl, 128, t);
        cpa_commit();
        cpa_wait0();
        __syncthreads();
        gemm64_w32(acc, sA, sBh, sBl, wm, wn, lane);
    }
    __syncthreads();   // smem reuse

    float* smT   = (float*)smh;         // [64][129] fp32
    float* sMean = smT + 64*129;
    float* sRstd = sMean + 64;
    const float* zb = g_zln + (size_t)t0 * DIM;
    int r0 = wm + (lane >> 2);
    int c0 = wn + (lane & 3) * 2;
    #pragma unroll
    for (int mt = 0; mt < 2; mt++)
        #pragma unroll
        for (int nt = 0; nt < 4; nt++) {
            int row = r0 + mt*16, col = c0 + nt*8;
            float b20 = b2[col], b21 = b2[col+1];
            float2 z0 = *(const float2*)&zb[(size_t)row*DIM + col];
            float2 z1 = *(const float2*)&zb[(size_t)(row+8)*DIM + col];
            smT[row*129 + col]       = acc[mt][nt][0] + b20 + z0.x;
            smT[row*129 + col + 1]   = acc[mt][nt][1] + b21 + z0.y;
            smT[(row+8)*129 + col]   = acc[mt][nt][2] + b20 + z1.x;
            smT[(row+8)*129 + col+1] = acc[mt][nt][3] + b21 + z1.y;
        }
    __syncthreads();
    if (t < 64) {
        float s = 0.f, q = 0.f;
        #pragma unroll 8
        for (int c = 0; c < 128; c++) {
            float v = smT[t*129 + c];
            s += v; q += v*v;
        }
        float mean = s * (1.0f / DIM);
        float var  = fmaxf(q * (1.0f / DIM) - mean*mean, 0.0f);
        sMean[t] = mean;
        sRstd[t] = 1.0f / sqrtf(var + 1e-5f);
    }
    __syncthreads();
    int b = t0 / P_;
    int prem = t0 - b * P_;
    #pragma unroll 4
    for (int k = 0; k < 32; k++) {
        int idx = k * 256 + t;
        int d = idx >> 6, p = idx & 63;   // consecutive t -> consecutive p
        float v = smT[p*129 + d];
        out[((size_t)(b*DIM + d))*P_ + prem + p] =
            (v - sMean[p]) * sRstd[p] * g2[d] + bb2[d];
    }
}

// ---------------- launch ----------------
extern "C" void kernel_launch(void* const* d_in, const int* in_sizes, int n_in,
                              void* d_out, int out_size) {
    const float* feature   = (const float*)d_in[0];
    const float* I_src     = (const float*)d_in[1];
    const float* I_tar_inv = (const float*)d_in[2];
    const float* E         = (const float*)d_in[3];
    const float* dis       = (const float*)d_in[4];
    const float* nrm       = (const float*)d_in[5];
    const float* conv_w    = (const float*)d_in[6];
    const float* bn_gamma  = (const float*)d_in[7];
    const float* bn_beta   = (const float*)d_in[8];
    const float* bn_mean   = (const float*)d_in[9];
    const float* bn_var    = (const float*)d_in[10];
    const float* ln1_g     = (const float*)d_in[11];
    const float* ln1_b     = (const float*)d_in[12];
    const float* ln2_g     = (const float*)d_in[13];
    const float* ln2_b     = (const float*)d_in[14];
    const float* mlp_w1    = (const float*)d_in[15];
    const float* mlp_b1    = (const float*)d_in[16];
    const float* mlp_w2    = (const float*)d_in[17];
    const float* mlp_b2    = (const float*)d_in[18];
    float* out = (float*)d_out;

    cudaFuncSetAttribute(k_conv_tc, cudaFuncAttributeMaxDynamicSharedMemorySize, SMEM_CONV);
    cudaFuncSetAttribute(k_mlp1_tc, cudaFuncAttributeMaxDynamicSharedMemorySize, SMEM_MLP1);
    cudaFuncSetAttribute(k_mlp2_tc, cudaFuncAttributeMaxDynamicSharedMemorySize, SMEM_MLP2);

    k_setup<<<48, 256>>>(I_src, I_tar_inv, E, dis, nrm, conv_w,
                         bn_gamma, bn_beta, bn_mean, bn_var, mlp_w1, mlp_w2);
    k_conv_tc<<<dim3(P_/128, BNV), 256, SMEM_CONV>>>(feature);
    k_attn<<<T2/8, 256>>>(ln1_g, ln1_b);
    k_mlp1_tc<<<dim3(T2/128, 4), 256, SMEM_MLP1>>>(mlp_b1);
    k_mlp2_tc<<<T2/64, 256, SMEM_MLP2>>>(mlp_b2, ln2_g, ln2_b, out);
}